// round 4
// baseline (speedup 1.0000x reference)
#include <cuda_runtime.h>

// ---------------------------------------------------------------------------
// Inverse DTCWT, 3 levels, fused col+row stages per level (smem tiles).
// Phase-specialized upsampling (t = 4n+q), window index map:
//   [0]=-4 [1]=-2 [2]=0 [3]=+2 [4]=-1 [5]=+1 [6]=+3 [7]=+5  (around 2n)
// ---------------------------------------------------------------------------

#define SH   0.70710678118654752440f
#define C_A  0.23389032f
#define C_B  0.5875183f
#define C_C  0.11430184f
#define C_D  0.76027237f
#define C_E  0.08832942f
#define C_F  0.03516384f

#define G0   0.35355339059327f
#define G1   0.70710678118655f
#define Q_E  (-0.08838834764832f)
#define Q_D  (-0.17677669529664f)
#define Q_F  0.53033008588991f

#define LP0(L) ( C_A*L[1] + C_B*L[2] - C_C*L[3])
#define LP1(L) ( C_D*L[5] - C_E*L[6] + C_F*L[7])
#define LP2(L) ( C_F*L[0] - C_E*L[1] + C_D*L[2])
#define LP3(L) (-C_C*L[4] + C_B*L[5] + C_A*L[6])
#define HP0(H) (-C_D*H[5] + C_E*H[6] - C_F*H[7])
#define HP1(H) ( C_A*H[1] + C_B*H[2] - C_C*H[3])
#define HP2(H) (-C_C*H[4] + C_B*H[5] + C_A*H[6])
#define HP3(H) (-C_F*H[0] + C_E*H[1] - C_D*H[2])

__device__ float g_z128[128 * 128 * 128];
__device__ float g_z256[128 * 256 * 256];

__device__ __forceinline__ int refl(int i, int n) {
    i = (i < 0) ? (-1 - i) : i;
    return (i >= n) ? (2 * n - 1 - i) : i;
}

__constant__ int cD8[8] = {-4, -2, 0, 2, -1, 1, 3, 5};

// ===========================================================================
// kAB: fused upsampling level. z:(128,r,c), yh:(128,6,r/2,c/2,2)
// -> Z:(128,2r,2c).  Tile: 32 rows x 64 cols of Z.
// ===========================================================================
#define AB_TH 32
#define AB_TW 64
#define AB_W  42       // y-tile width: TW/2 + 10
#define AB_ST 43       // smem row stride (odd)

// scalar column filter (verbatim R2 logic) -> writes 4 rows into smem col
__device__ __forceinline__ void
kA_col_scalar(const float* __restrict__ z, const float* __restrict__ yh,
              float* __restrict__ y1t, float* __restrict__ y2t,
              int r, int c, int b, int n_g, int n_l, int jc, int jc_l) {
    int rh = r >> 1;
    int pj = jc & 1;
    int rw[8], oB[8];
    float s1v[8], s2v[8];
#pragma unroll
    for (int t = 0; t < 8; t++) {
        int rr = refl(2 * n_g + cD8[t], r);
        rw[t] = rr;
        int ii = rr >> 1, pi = rr & 1;
        oB[t] = ii * c + (pi ^ pj);
        s1v[t] = (pi & pj) ? -1.f : 1.f;
        s2v[t] = (pi & (pj ^ 1)) ? -1.f : 1.f;
    }
    const float* zb = z + (size_t)b * r * c + jc;
    const float* yb = yh + (size_t)b * 6 * rh * c + 2 * (jc >> 1);
    const int sb = rh * c;

    float L[8], H[8];
#pragma unroll
    for (int t = 0; t < 8; t++) L[t] = __ldg(zb + rw[t] * c);
#pragma unroll
    for (int t = 0; t < 8; t++)
        H[t] = s1v[t] * __ldg(yb + oB[t]) + s2v[t] * __ldg(yb + 5 * sb + oB[t]);  // lh

    float* o1 = y1t + (4 * n_l) * AB_ST + jc_l;
    o1[0]         = LP0(L) + SH * HP0(H);
    o1[AB_ST]     = LP1(L) + SH * HP1(H);
    o1[2 * AB_ST] = LP2(L) + SH * HP2(H);
    o1[3 * AB_ST] = LP3(L) + SH * HP3(H);

#pragma unroll
    for (int t = 0; t < 8; t++)
        L[t] = s1v[t] * __ldg(yb + 2 * sb + oB[t]) + s2v[t] * __ldg(yb + 3 * sb + oB[t]);  // hl
#pragma unroll
    for (int t = 0; t < 8; t++)
        H[t] = s1v[t] * __ldg(yb + 1 * sb + oB[t]) + s2v[t] * __ldg(yb + 4 * sb + oB[t]);  // hh

    float* o2 = y2t + (4 * n_l) * AB_ST + jc_l;
    o2[0]         = SH * (LP0(L) + HP0(H));
    o2[AB_ST]     = SH * (LP1(L) + HP1(H));
    o2[2 * AB_ST] = SH * (LP2(L) + HP2(H));
    o2[3 * AB_ST] = SH * (LP3(L) + HP3(H));
}

__global__ void __launch_bounds__(256)
kAB(const float* __restrict__ z, const float* __restrict__ yh,
    float* __restrict__ Z, int r, int c) {
    __shared__ float y1t[AB_TH * AB_ST];
    __shared__ float y2t[AB_TH * AB_ST];

    int b = blockIdx.z;
    int rh = r >> 1, ch = c >> 1;
    int i0 = blockIdx.y * AB_TH;   // output row base
    int u0 = blockIdx.x * AB_TW;   // output col base
    int c0h = u0 >> 1;             // y/z-domain col base
    int n0 = i0 >> 2;
    int tid = threadIdx.x;

    // ---------------- phase 1: 8 n x 21 col-pairs = 168 items ---------------
    if (tid < 168) {
        int cp = tid % 21;
        int n_l = tid / 21;
        int n_g = n0 + n_l;
        int e = c0h - 4 + 2 * cp;  // raw even column
        bool fast = (e >= 0) && (e + 1 < c) && (n_g >= 2) && (n_g <= rh - 3);
        if (fast) {
            int jj = e >> 1;
            const float2* z2 = (const float2*)z + (size_t)b * r * ch + jj;
            const float2* yb2 = (const float2*)yh + (size_t)b * 6 * rh * ch + jj;
            const int sstr = rh * ch;
            int base = 2 * n_g;

            float2 Lz[8];
            Lz[0] = __ldg(z2 + (base - 4) * ch);
            Lz[1] = __ldg(z2 + (base - 2) * ch);
            Lz[2] = __ldg(z2 + base * ch);
            Lz[3] = __ldg(z2 + (base + 2) * ch);
            Lz[4] = __ldg(z2 + (base - 1) * ch);
            Lz[5] = __ldg(z2 + (base + 1) * ch);
            Lz[6] = __ldg(z2 + (base + 3) * ch);
            Lz[7] = __ldg(z2 + (base + 5) * ch);
            float L0[8], L1[8];
#pragma unroll
            for (int t = 0; t < 8; t++) { L0[t] = Lz[t].x; L1[t] = Lz[t].y; }

#define LOAD_PAIR5(S1, S2, B0, B1)                                            \
    {                                                                         \
        float2 w1[5], w2[5];                                                  \
        _Pragma("unroll") for (int t = 0; t < 5; t++) {                       \
            w1[t] = __ldg(yb2 + ((S1) * sstr + (n_g - 2 + t) * ch));          \
            w2[t] = __ldg(yb2 + ((S2) * sstr + (n_g - 2 + t) * ch));          \
        }                                                                     \
        _Pragma("unroll") for (int t = 0; t < 4; t++) {                       \
            B0[t] = w1[t].x + w2[t].x;                                        \
            B1[t] = w1[t].y + w2[t].y;                                        \
            B0[4 + t] = w1[t + 1].y - w2[t + 1].y;                            \
            B1[4 + t] = w2[t + 1].x - w1[t + 1].x;                            \
        }                                                                     \
    }
            float* o1 = y1t + (4 * n_l) * AB_ST + 2 * cp;
            {
                float B0[8], B1[8];
                LOAD_PAIR5(0, 5, B0, B1);  // lh
                o1[0]             = LP0(L0) + SH * HP0(B0);
                o1[1]             = LP0(L1) + SH * HP0(B1);
                o1[AB_ST]         = LP1(L0) + SH * HP1(B0);
                o1[AB_ST + 1]     = LP1(L1) + SH * HP1(B1);
                o1[2 * AB_ST]     = LP2(L0) + SH * HP2(B0);
                o1[2 * AB_ST + 1] = LP2(L1) + SH * HP2(B1);
                o1[3 * AB_ST]     = LP3(L0) + SH * HP3(B0);
                o1[3 * AB_ST + 1] = LP3(L1) + SH * HP3(B1);
            }
            float* o2 = y2t + (4 * n_l) * AB_ST + 2 * cp;
            {
                float A0[8], A1[8], B0[8], B1[8];
                LOAD_PAIR5(2, 3, A0, A1);  // hl
                LOAD_PAIR5(1, 4, B0, B1);  // hh
                o2[0]             = SH * (LP0(A0) + HP0(B0));
                o2[1]             = SH * (LP0(A1) + HP0(B1));
                o2[AB_ST]         = SH * (LP1(A0) + HP1(B0));
                o2[AB_ST + 1]     = SH * (LP1(A1) + HP1(B1));
                o2[2 * AB_ST]     = SH * (LP2(A0) + HP2(B0));
                o2[2 * AB_ST + 1] = SH * (LP2(A1) + HP2(B1));
                o2[3 * AB_ST]     = SH * (LP3(A0) + HP3(B0));
                o2[3 * AB_ST + 1] = SH * (LP3(A1) + HP3(B1));
            }
#undef LOAD_PAIR5
        } else {
#pragma unroll
            for (int s = 0; s < 2; s++) {
                int jc_l = 2 * cp + s;
                int jc = refl(c0h - 4 + jc_l, c);
                kA_col_scalar(z, yh, y1t, y2t, r, c, b, n_g, n_l, jc, jc_l);
            }
        }
    }
    __syncthreads();

    // ---------------- phase 2: 512 items (32 rows x 16 float4) --------------
    int C2 = 2 * c;
#pragma unroll
    for (int it = 0; it < 2; it++) {
        int item = tid + it * 256;
        int p = item & 15;
        int i_l = item >> 4;
        const float* s1 = y1t + i_l * AB_ST + 2 * p;
        const float* s2 = y2t + i_l * AB_ST + 2 * p;
        float L[8], H[8];
        L[0] = s1[0]; L[1] = s1[2]; L[2] = s1[4]; L[3] = s1[6];
        L[4] = s1[3]; L[5] = s1[5]; L[6] = s1[7]; L[7] = s1[9];
        H[0] = s2[0]; H[1] = s2[2]; H[2] = s2[4]; H[3] = s2[6];
        H[4] = s2[3]; H[5] = s2[5]; H[6] = s2[7]; H[7] = s2[9];
        float4 o;
        o.x = LP0(L) + HP0(H);
        o.y = LP1(L) + HP1(H);
        o.z = LP2(L) + HP2(H);
        o.w = LP3(L) + HP3(H);
        reinterpret_cast<float4*>(Z + ((size_t)b * 2 * r + i0 + i_l) * C2 + u0)[p] = o;
    }
}

// ===========================================================================
// kCD: fused final level. z:(128,R,C), yh0:(128,6,R/2,C/2,2) -> out:(128,R,C)
// Tile: 32 x 32 of out. y-tile: 32 rows x 40 cols (halo -2..+5).
// ===========================================================================
#define CD_W  40
#define CD_ST 41

__device__ __forceinline__ void
kC_col_scalar(const float* __restrict__ z, const float* __restrict__ yh,
              float* __restrict__ y1t, float* __restrict__ y2t,
              int R, int C, int b, int m_g, int m_l, int jc, int jc_l) {
    int i0 = 2 * m_g;
    int rh = R >> 1;
    int pj = jc & 1;
    int o6[6];
    float s1v[6], s2v[6];
    int rr[6];
#pragma unroll
    for (int t = 0; t < 6; t++) {
        int rx = refl(i0 - 2 + t, R);
        rr[t] = rx;
        int ii = rx >> 1, pi = rx & 1;
        o6[t] = ii * C + (pi ^ pj);
        s1v[t] = (pi & pj) ? -1.f : 1.f;
        s2v[t] = (pi & (pj ^ 1)) ? -1.f : 1.f;
    }
    const float* zb = z + (size_t)b * R * C + jc;
    const float* yb = yh + (size_t)b * 6 * rh * C + 2 * (jc >> 1);
    const int sb = rh * C;

    float zr[4];
#pragma unroll
    for (int t = 0; t < 4; t++) zr[t] = __ldg(zb + rr[t + 1] * C);

    float lr[6], hlr[6], hhr[6];
#pragma unroll
    for (int t = 0; t < 6; t++) {
        lr[t]  = s1v[t] * __ldg(yb + o6[t])          + s2v[t] * __ldg(yb + 5 * sb + o6[t]);
        hlr[t] = s1v[t] * __ldg(yb + 2 * sb + o6[t]) + s2v[t] * __ldg(yb + 3 * sb + o6[t]);
        hhr[t] = s1v[t] * __ldg(yb + 1 * sb + o6[t]) + s2v[t] * __ldg(yb + 4 * sb + o6[t]);
    }
    float* o1 = y1t + (2 * m_l) * CD_ST + jc_l;
    float* o2 = y2t + (2 * m_l) * CD_ST + jc_l;
    o1[0]     = G0 * (zr[0] + zr[2]) + G1 * zr[1]
              + SH * (Q_E * (lr[0] + lr[4]) + Q_D * (lr[1] + lr[3]) + Q_F * lr[2]);
    o1[CD_ST] = G0 * (zr[1] + zr[3]) + G1 * zr[2]
              + SH * (Q_E * (lr[1] + lr[5]) + Q_D * (lr[2] + lr[4]) + Q_F * lr[3]);
    o2[0]     = SH * (G0 * (hlr[1] + hlr[3]) + G1 * hlr[2]
              + Q_E * (hhr[0] + hhr[4]) + Q_D * (hhr[1] + hhr[3]) + Q_F * hhr[2]);
    o2[CD_ST] = SH * (G0 * (hlr[2] + hlr[4]) + G1 * hlr[3]
              + Q_E * (hhr[1] + hhr[5]) + Q_D * (hhr[2] + hhr[4]) + Q_F * hhr[3]);
}

__global__ void __launch_bounds__(256)
kCD(const float* __restrict__ z, const float* __restrict__ yh,
    float* __restrict__ out, int R, int C) {
    __shared__ float y1t[32 * CD_ST];
    __shared__ float y2t[32 * CD_ST];

    int b = blockIdx.z;
    int rh = R >> 1, chb = C >> 1;
    int i0 = blockIdx.y * 32;
    int u0 = blockIdx.x * 32;
    int m0 = i0 >> 1;
    int tid = threadIdx.x;

    // ---------------- phase 1: 16 m x 20 col-pairs = 320 items --------------
    for (int item = tid; item < 320; item += 256) {
        int cp = item % 20;
        int m_l = item / 20;
        int m_g = m0 + m_l;
        int e = u0 - 2 + 2 * cp;
        bool fast = (e >= 0) && (e + 1 < C) && (m_g >= 1) && (m_g <= rh - 2);
        if (fast) {
            int jj = e >> 1;
            const float2* z2 = (const float2*)z + (size_t)b * R * chb + jj;
            const float2* yb2 = (const float2*)yh + (size_t)b * 6 * rh * chb + jj;
            const int sstr = rh * chb;
            int i0g = 2 * m_g;

            float2 zr[4];
#pragma unroll
            for (int t = 0; t < 4; t++) zr[t] = __ldg(z2 + (i0g - 1 + t) * chb);

#define LOAD_PAIR3(S1, S2, B0, B1)                                            \
    {                                                                         \
        float2 w1[3], w2[3];                                                  \
        _Pragma("unroll") for (int t = 0; t < 3; t++) {                       \
            w1[t] = __ldg(yb2 + ((S1) * sstr + (m_g - 1 + t) * chb));         \
            w2[t] = __ldg(yb2 + ((S2) * sstr + (m_g - 1 + t) * chb));         \
        }                                                                     \
        _Pragma("unroll") for (int t = 0; t < 3; t++) {                       \
            B0[2 * t] = w1[t].x + w2[t].x;                                    \
            B1[2 * t] = w1[t].y + w2[t].y;                                    \
            B0[2 * t + 1] = w1[t].y - w2[t].y;                                \
            B1[2 * t + 1] = w2[t].x - w1[t].x;                                \
        }                                                                     \
    }
            float lr0[6], lr1[6], hl0[6], hl1[6], hh0[6], hh1[6];
            LOAD_PAIR3(0, 5, lr0, lr1);
            LOAD_PAIR3(2, 3, hl0, hl1);
            LOAD_PAIR3(1, 4, hh0, hh1);
#undef LOAD_PAIR3

            float* o1 = y1t + (2 * m_l) * CD_ST + 2 * cp;
            float* o2 = y2t + (2 * m_l) * CD_ST + 2 * cp;
            o1[0] = G0 * (zr[0].x + zr[2].x) + G1 * zr[1].x
                  + SH * (Q_E * (lr0[0] + lr0[4]) + Q_D * (lr0[1] + lr0[3]) + Q_F * lr0[2]);
            o1[1] = G0 * (zr[0].y + zr[2].y) + G1 * zr[1].y
                  + SH * (Q_E * (lr1[0] + lr1[4]) + Q_D * (lr1[1] + lr1[3]) + Q_F * lr1[2]);
            o1[CD_ST] = G0 * (zr[1].x + zr[3].x) + G1 * zr[2].x
                  + SH * (Q_E * (lr0[1] + lr0[5]) + Q_D * (lr0[2] + lr0[4]) + Q_F * lr0[3]);
            o1[CD_ST + 1] = G0 * (zr[1].y + zr[3].y) + G1 * zr[2].y
                  + SH * (Q_E * (lr1[1] + lr1[5]) + Q_D * (lr1[2] + lr1[4]) + Q_F * lr1[3]);
            o2[0] = SH * (G0 * (hl0[1] + hl0[3]) + G1 * hl0[2]
                  + Q_E * (hh0[0] + hh0[4]) + Q_D * (hh0[1] + hh0[3]) + Q_F * hh0[2]);
            o2[1] = SH * (G0 * (hl1[1] + hl1[3]) + G1 * hl1[2]
                  + Q_E * (hh1[0] + hh1[4]) + Q_D * (hh1[1] + hh1[3]) + Q_F * hh1[2]);
            o2[CD_ST] = SH * (G0 * (hl0[2] + hl0[4]) + G1 * hl0[3]
                  + Q_E * (hh0[1] + hh0[5]) + Q_D * (hh0[2] + hh0[4]) + Q_F * hh0[3]);
            o2[CD_ST + 1] = SH * (G0 * (hl1[2] + hl1[4]) + G1 * hl1[3]
                  + Q_E * (hh1[1] + hh1[5]) + Q_D * (hh1[2] + hh1[4]) + Q_F * hh1[3]);
        } else {
#pragma unroll
            for (int s = 0; s < 2; s++) {
                int jc_l = 2 * cp + s;
                int jc = refl(u0 - 2 + jc_l, C);
                kC_col_scalar(z, yh, y1t, y2t, R, C, b, m_g, m_l, jc, jc_l);
            }
        }
    }
    __syncthreads();

    // ---------------- phase 2: 256 items (32 rows x 8 float4) ---------------
    {
        int p = tid & 7;
        int i_l = tid >> 3;
        const float* s1 = y1t + i_l * CD_ST;
        const float* s2 = y2t + i_l * CD_ST;
        float a[6], v[8];
#pragma unroll
        for (int t = 0; t < 6; t++) a[t] = s1[4 * p + 1 + t];
#pragma unroll
        for (int t = 0; t < 8; t++) v[t] = s2[4 * p + t];
        float4 o;
        o.x = G0 * (a[0] + a[2]) + G1 * a[1] + Q_E * (v[0] + v[4]) + Q_D * (v[1] + v[3]) + Q_F * v[2];
        o.y = G0 * (a[1] + a[3]) + G1 * a[2] + Q_E * (v[1] + v[5]) + Q_D * (v[2] + v[4]) + Q_F * v[3];
        o.z = G0 * (a[2] + a[4]) + G1 * a[3] + Q_E * (v[2] + v[6]) + Q_D * (v[3] + v[5]) + Q_F * v[4];
        o.w = G0 * (a[3] + a[5]) + G1 * a[4] + Q_E * (v[3] + v[7]) + Q_D * (v[4] + v[6]) + Q_F * v[5];
        reinterpret_cast<float4*>(out + ((size_t)b * R + i0 + i_l) * C + u0)[p] = o;
    }
}

extern "C" void kernel_launch(void* const* d_in, const int* in_sizes, int n_in,
                              void* d_out, int out_size) {
    const float *yl = nullptr, *yh0 = nullptr, *yh1 = nullptr, *yh2 = nullptr;
    for (int i = 0; i < n_in; i++) {
        switch (in_sizes[i]) {
            case 524288:   yl  = (const float*)d_in[i]; break;  // 128*64*64
            case 25165824: yh0 = (const float*)d_in[i]; break;  // 128*6*128*128*2
            case 6291456:  yh1 = (const float*)d_in[i]; break;  // 128*6*64*64*2
            case 1572864:  yh2 = (const float*)d_in[i]; break;  // 128*6*32*32*2
            default: break;
        }
    }

    float *pz128, *pz256;
    cudaGetSymbolAddress((void**)&pz128, g_z128);
    cudaGetSymbolAddress((void**)&pz256, g_z256);

    // Level 1: (64,64) -> (128,128)
    kAB<<<dim3(2, 4, 128), 256>>>(yl, yh2, pz128, 64, 64);
    // Level 2: (128,128) -> (256,256)
    kAB<<<dim3(4, 8, 128), 256>>>(pz128, yh1, pz256, 128, 128);
    // Final level: (256,256) -> out
    kCD<<<dim3(8, 8, 128), 256>>>(pz256, yh0, (float*)d_out, 256, 256);
}

// round 6
// speedup vs baseline: 1.2204x; 1.2204x over previous
#include <cuda_runtime.h>

// ---------------------------------------------------------------------------
// Inverse DTCWT, 3 levels. Separate col/row kernels (R3 structure) but the
// column-stage outputs are written into COLUMN-PADDED buffers with symmetric
// reflection pre-baked into halo columns, so the row-stage kernels are fully
// branch-free and vectorized.
// Upsampling window index map (around 2n):
//   [0]=-4 [1]=-2 [2]=0 [3]=+2 [4]=-1 [5]=+1 [6]=+3 [7]=+5
// ---------------------------------------------------------------------------

#define SH   0.70710678118654752440f
#define C_A  0.23389032f
#define C_B  0.5875183f
#define C_C  0.11430184f
#define C_D  0.76027237f
#define C_E  0.08832942f
#define C_F  0.03516384f

#define G0   0.35355339059327f
#define G1   0.70710678118655f
#define Q_E  (-0.08838834764832f)
#define Q_D  (-0.17677669529664f)
#define Q_F  0.53033008588991f

#define LP0(L) ( C_A*L[1] + C_B*L[2] - C_C*L[3])
#define LP1(L) ( C_D*L[5] - C_E*L[6] + C_F*L[7])
#define LP2(L) ( C_F*L[0] - C_E*L[1] + C_D*L[2])
#define LP3(L) (-C_C*L[4] + C_B*L[5] + C_A*L[6])
#define HP0(H) (-C_D*H[5] + C_E*H[6] - C_F*H[7])
#define HP1(H) ( C_A*H[1] + C_B*H[2] - C_C*H[3])
#define HP2(H) (-C_C*H[4] + C_B*H[5] + C_A*H[6])
#define HP3(H) (-C_F*H[0] + C_E*H[1] - C_D*H[2])

// Scratch: padded y buffers.
__device__ float g_y1[128 * 256 * 268];
__device__ float g_y2[128 * 256 * 268];
__device__ float g_z128[128 * 128 * 128];
__device__ float g_z256[128 * 256 * 256];

__device__ __forceinline__ int refl(int i, int n) {
    i = (i < 0) ? (-1 - i) : i;
    return (i >= n) ? (2 * n - 1 - i) : i;
}

__host__ __device__ constexpr int ilog2c(int v) { return v <= 1 ? 0 : 1 + ilog2c(v >> 1); }

// ===========================================================================
// kA scalar path (any row n, any source column jc; writes padded col pc).
// ===========================================================================
template <int RI, int CI>
__device__ void kA_scalar(const float* __restrict__ z, const float* __restrict__ yh,
                          float* __restrict__ y1p, float* __restrict__ y2p,
                          int b, int n, int jc, int pc) {
    constexpr int rh = RI / 2, PS = CI + 12;
    const int d8[8] = {-4, -2, 0, 2, -1, 1, 3, 5};
    int pj = jc & 1;
    int rw[8], oB[8];
    float s1v[8], s2v[8];
#pragma unroll
    for (int t = 0; t < 8; t++) {
        int rr = refl(2 * n + d8[t], RI);
        rw[t] = rr;
        int ii = rr >> 1, pi = rr & 1;
        oB[t] = ii * CI + (pi ^ pj);
        s1v[t] = (pi & pj) ? -1.f : 1.f;
        s2v[t] = (pi & (pj ^ 1)) ? -1.f : 1.f;
    }
    const float* zb = z + (size_t)b * RI * CI + jc;
    const float* yb = yh + (size_t)b * 6 * rh * CI + 2 * (jc >> 1);
    const int sb = rh * CI;

    float L[8], H[8];
#pragma unroll
    for (int t = 0; t < 8; t++) L[t] = __ldg(zb + rw[t] * CI);
#pragma unroll
    for (int t = 0; t < 8; t++)
        H[t] = s1v[t] * __ldg(yb + oB[t]) + s2v[t] * __ldg(yb + 5 * sb + oB[t]);  // lh

    float* o1 = y1p + ((size_t)b * 2 * RI + 4 * n) * PS + pc;
    o1[0]      = LP0(L) + SH * HP0(H);
    o1[PS]     = LP1(L) + SH * HP1(H);
    o1[2 * PS] = LP2(L) + SH * HP2(H);
    o1[3 * PS] = LP3(L) + SH * HP3(H);

#pragma unroll
    for (int t = 0; t < 8; t++)
        L[t] = s1v[t] * __ldg(yb + 2 * sb + oB[t]) + s2v[t] * __ldg(yb + 3 * sb + oB[t]);  // hl
#pragma unroll
    for (int t = 0; t < 8; t++)
        H[t] = s1v[t] * __ldg(yb + 1 * sb + oB[t]) + s2v[t] * __ldg(yb + 4 * sb + oB[t]);  // hh

    float* o2 = y2p + ((size_t)b * 2 * RI + 4 * n) * PS + pc;
    o2[0]      = SH * (LP0(L) + HP0(H));
    o2[PS]     = SH * (LP1(L) + HP1(H));
    o2[2 * PS] = SH * (LP2(L) + HP2(H));
    o2[3 * PS] = SH * (LP3(L) + HP3(H));
}

// ===========================================================================
// kA: column upsampling. z:(128,RI,CI), yh:(128,6,RI/2,CI/2,2)
//  -> y1p,y2p:(128, 2*RI, CI+12), data at padded cols 4..CI+9 (refl baked in).
// Thread = (b, n, jp); jp < CI/2: interior pair; else one of 5 halo pairs.
// ===========================================================================
template <int RI, int CI>
__global__ void __launch_bounds__(256)
kA(const float* __restrict__ z, const float* __restrict__ yh,
   float* __restrict__ y1p, float* __restrict__ y2p) {
    constexpr int rh = RI / 2, ch = CI / 2, JP = ch + 5, PS = CI + 12, PS2 = PS / 2;
    unsigned idx = blockIdx.x * 256u + threadIdx.x;
    int jp = idx % JP;
    int n = (idx / JP) % rh;
    int b = idx / (JP * rh);

    if (jp < ch && n >= 2 && n <= rh - 3) {
        const float2* z2 = (const float2*)z + (size_t)b * RI * ch + jp;
        const float2* yb2 = (const float2*)yh + (size_t)b * 6 * rh * ch + jp;
        const int sstr = rh * ch;
        int base = 2 * n;

        float2 Lz[8];
        Lz[0] = __ldg(z2 + (base - 4) * ch);
        Lz[1] = __ldg(z2 + (base - 2) * ch);
        Lz[2] = __ldg(z2 + base * ch);
        Lz[3] = __ldg(z2 + (base + 2) * ch);
        Lz[4] = __ldg(z2 + (base - 1) * ch);
        Lz[5] = __ldg(z2 + (base + 1) * ch);
        Lz[6] = __ldg(z2 + (base + 3) * ch);
        Lz[7] = __ldg(z2 + (base + 5) * ch);
        float L0[8], L1[8];
#pragma unroll
        for (int t = 0; t < 8; t++) { L0[t] = Lz[t].x; L1[t] = Lz[t].y; }

#define LOAD_PAIR5(S1, S2, B0, B1)                                            \
    {                                                                         \
        float2 w1[5], w2[5];                                                  \
        _Pragma("unroll") for (int t = 0; t < 5; t++) {                       \
            w1[t] = __ldg(yb2 + ((S1) * sstr + (n - 2 + t) * ch));            \
            w2[t] = __ldg(yb2 + ((S2) * sstr + (n - 2 + t) * ch));            \
        }                                                                     \
        _Pragma("unroll") for (int t = 0; t < 4; t++) {                       \
            B0[t] = w1[t].x + w2[t].x;                                        \
            B1[t] = w1[t].y + w2[t].y;                                        \
            B0[4 + t] = w1[t + 1].y - w2[t + 1].y;                            \
            B1[4 + t] = w2[t + 1].x - w1[t + 1].x;                            \
        }                                                                     \
    }
        float2* o1 = (float2*)y1p + ((size_t)b * 2 * RI + 4 * n) * PS2 + (jp + 2);
        {
            float B0[8], B1[8];
            LOAD_PAIR5(0, 5, B0, B1);  // lh
            float2 o;
            o.x = LP0(L0) + SH * HP0(B0); o.y = LP0(L1) + SH * HP0(B1); o1[0] = o;
            o.x = LP1(L0) + SH * HP1(B0); o.y = LP1(L1) + SH * HP1(B1); o1[PS2] = o;
            o.x = LP2(L0) + SH * HP2(B0); o.y = LP2(L1) + SH * HP2(B1); o1[2 * PS2] = o;
            o.x = LP3(L0) + SH * HP3(B0); o.y = LP3(L1) + SH * HP3(B1); o1[3 * PS2] = o;
        }
        float2* o2 = (float2*)y2p + ((size_t)b * 2 * RI + 4 * n) * PS2 + (jp + 2);
        {
            float A0[8], A1[8], B0[8], B1[8];
            LOAD_PAIR5(2, 3, A0, A1);  // hl
            LOAD_PAIR5(1, 4, B0, B1);  // hh
            float2 o;
            o.x = SH * (LP0(A0) + HP0(B0)); o.y = SH * (LP0(A1) + HP0(B1)); o2[0] = o;
            o.x = SH * (LP1(A0) + HP1(B0)); o.y = SH * (LP1(A1) + HP1(B1)); o2[PS2] = o;
            o.x = SH * (LP2(A0) + HP2(B0)); o.y = SH * (LP2(A1) + HP2(B1)); o2[2 * PS2] = o;
            o.x = SH * (LP3(A0) + HP3(B0)); o.y = SH * (LP3(A1) + HP3(B1)); o2[3 * PS2] = o;
        }
#undef LOAD_PAIR5
    } else if (jp < ch) {
        kA_scalar<RI, CI>(z, yh, y1p, y2p, b, n, 2 * jp, 2 * jp + 4);
        kA_scalar<RI, CI>(z, yh, y1p, y2p, b, n, 2 * jp + 1, 2 * jp + 5);
    } else {
        int hp = jp - ch;
        int pc0 = (hp < 2) ? 2 * hp : (CI + 2 * hp);
#pragma unroll
        for (int s = 0; s < 2; s++) {
            int pc = pc0 + s;
            int jc = refl(pc - 4, CI);
            kA_scalar<RI, CI>(z, yh, y1p, y2p, b, n, jc, pc);
        }
    }
}

// ===========================================================================
// kB: branch-free row upsampling. y1p,y2p:(128, RO, CO/2+12 padded)
//  -> Z:(128, RO, CO). Thread = (row, n), float4 store at col 4n.
// ===========================================================================
template <int RO, int CO>
__global__ void __launch_bounds__(256)
kB(const float* __restrict__ y1p, const float* __restrict__ y2p,
   float* __restrict__ Z) {
    constexpr int ch = CO / 4;               // n range
    constexpr int PS2 = (CO / 2 + 12) / 2;   // padded float2 row stride
    constexpr int LCH = ilog2c(ch);
    unsigned idx = blockIdx.x * 256u + threadIdx.x;
    int n = idx & (ch - 1);
    int row = idx >> LCH;  // b*RO + i

    const float2* q1 = (const float2*)y1p + (size_t)row * PS2 + n;
    const float2* q2 = (const float2*)y2p + (size_t)row * PS2 + n;
    float2 u0 = __ldg(q1), u1 = __ldg(q1 + 1), u2 = __ldg(q1 + 2),
           u3 = __ldg(q1 + 3), u4 = __ldg(q1 + 4);
    float2 w0 = __ldg(q2), w1 = __ldg(q2 + 1), w2 = __ldg(q2 + 2),
           w3 = __ldg(q2 + 3), w4 = __ldg(q2 + 4);
    float L[8], H[8];
    L[0] = u0.x; L[1] = u1.x; L[2] = u2.x; L[3] = u3.x;
    L[4] = u1.y; L[5] = u2.y; L[6] = u3.y; L[7] = u4.y;
    H[0] = w0.x; H[1] = w1.x; H[2] = w2.x; H[3] = w3.x;
    H[4] = w1.y; H[5] = w2.y; H[6] = w3.y; H[7] = w4.y;
    float4 o;
    o.x = LP0(L) + HP0(H);
    o.y = LP1(L) + HP1(H);
    o.z = LP2(L) + HP2(H);
    o.w = LP3(L) + HP3(H);
    reinterpret_cast<float4*>(Z + (size_t)row * CO)[n] = o;
}

// ===========================================================================
// kC scalar path (final-level column filter, any m / source col jc -> pc).
// ===========================================================================
template <int RI, int CI>
__device__ void kC_scalar(const float* __restrict__ z, const float* __restrict__ yh,
                          float* __restrict__ y1p, float* __restrict__ y2p,
                          int b, int m, int jc, int pc) {
    constexpr int rh = RI / 2, PS = CI + 10;
    int i0 = 2 * m;
    int pj = jc & 1;
    int o6[6];
    float s1v[6], s2v[6];
    int rr[6];
#pragma unroll
    for (int t = 0; t < 6; t++) {
        int rx = refl(i0 - 2 + t, RI);
        rr[t] = rx;
        int ii = rx >> 1, pi = rx & 1;
        o6[t] = ii * CI + (pi ^ pj);
        s1v[t] = (pi & pj) ? -1.f : 1.f;
        s2v[t] = (pi & (pj ^ 1)) ? -1.f : 1.f;
    }
    const float* zb = z + (size_t)b * RI * CI + jc;
    const float* yb = yh + (size_t)b * 6 * rh * CI + 2 * (jc >> 1);
    const int sb = rh * CI;

    float zr[4];
#pragma unroll
    for (int t = 0; t < 4; t++) zr[t] = __ldg(zb + rr[t + 1] * CI);

    float lr[6], hlr[6], hhr[6];
#pragma unroll
    for (int t = 0; t < 6; t++) {
        lr[t]  = s1v[t] * __ldg(yb + o6[t])          + s2v[t] * __ldg(yb + 5 * sb + o6[t]);
        hlr[t] = s1v[t] * __ldg(yb + 2 * sb + o6[t]) + s2v[t] * __ldg(yb + 3 * sb + o6[t]);
        hhr[t] = s1v[t] * __ldg(yb + 1 * sb + o6[t]) + s2v[t] * __ldg(yb + 4 * sb + o6[t]);
    }
    float* o1 = y1p + ((size_t)b * RI + i0) * PS + pc;
    float* o2 = y2p + ((size_t)b * RI + i0) * PS + pc;
    o1[0]  = G0 * (zr[0] + zr[2]) + G1 * zr[1]
           + SH * (Q_E * (lr[0] + lr[4]) + Q_D * (lr[1] + lr[3]) + Q_F * lr[2]);
    o1[PS] = G0 * (zr[1] + zr[3]) + G1 * zr[2]
           + SH * (Q_E * (lr[1] + lr[5]) + Q_D * (lr[2] + lr[4]) + Q_F * lr[3]);
    o2[0]  = SH * (G0 * (hlr[1] + hlr[3]) + G1 * hlr[2]
           + Q_E * (hhr[0] + hhr[4]) + Q_D * (hhr[1] + hhr[3]) + Q_F * hhr[2]);
    o2[PS] = SH * (G0 * (hlr[2] + hlr[4]) + G1 * hlr[3]
           + Q_E * (hhr[1] + hhr[5]) + Q_D * (hhr[2] + hhr[4]) + Q_F * hhr[3]);
}

// ===========================================================================
// kC: final-level column filters -> padded y1p,y2p (128, RI, CI+10), offset 4.
// ===========================================================================
template <int RI, int CI>
__global__ void __launch_bounds__(256)
kC(const float* __restrict__ z, const float* __restrict__ yh,
   float* __restrict__ y1p, float* __restrict__ y2p) {
    constexpr int rh = RI / 2, chb = CI / 2, JP = chb + 5, PS = CI + 10, PS2 = PS / 2;
    unsigned idx = blockIdx.x * 256u + threadIdx.x;
    int jp = idx % JP;
    int m = (idx / JP) % rh;
    int b = idx / (JP * rh);

    if (jp < chb && m >= 1 && m <= rh - 2) {
        int i0 = 2 * m;
        const float2* z2 = (const float2*)z + (size_t)b * RI * chb + jp;
        const float2* yb2 = (const float2*)yh + (size_t)b * 6 * rh * chb + jp;
        const int sstr = rh * chb;

        float2 zr[4];
#pragma unroll
        for (int t = 0; t < 4; t++) zr[t] = __ldg(z2 + (i0 - 1 + t) * chb);

#define LOAD_PAIR3(S1, S2, B0, B1)                                            \
    {                                                                         \
        float2 w1[3], w2[3];                                                  \
        _Pragma("unroll") for (int t = 0; t < 3; t++) {                       \
            w1[t] = __ldg(yb2 + ((S1) * sstr + (m - 1 + t) * chb));           \
            w2[t] = __ldg(yb2 + ((S2) * sstr + (m - 1 + t) * chb));           \
        }                                                                     \
        _Pragma("unroll") for (int t = 0; t < 3; t++) {                       \
            B0[2 * t] = w1[t].x + w2[t].x;                                    \
            B1[2 * t] = w1[t].y + w2[t].y;                                    \
            B0[2 * t + 1] = w1[t].y - w2[t].y;                                \
            B1[2 * t + 1] = w2[t].x - w1[t].x;                                \
        }                                                                     \
    }
        float lr0[6], lr1[6], hl0[6], hl1[6], hh0[6], hh1[6];
        LOAD_PAIR3(0, 5, lr0, lr1);
        LOAD_PAIR3(2, 3, hl0, hl1);
        LOAD_PAIR3(1, 4, hh0, hh1);
#undef LOAD_PAIR3

        float2* o1 = (float2*)y1p + ((size_t)b * RI + i0) * PS2 + (jp + 2);
        float2* o2 = (float2*)y2p + ((size_t)b * RI + i0) * PS2 + (jp + 2);
        float2 o;
        o.x = G0 * (zr[0].x + zr[2].x) + G1 * zr[1].x
            + SH * (Q_E * (lr0[0] + lr0[4]) + Q_D * (lr0[1] + lr0[3]) + Q_F * lr0[2]);
        o.y = G0 * (zr[0].y + zr[2].y) + G1 * zr[1].y
            + SH * (Q_E * (lr1[0] + lr1[4]) + Q_D * (lr1[1] + lr1[3]) + Q_F * lr1[2]);
        o1[0] = o;
        o.x = G0 * (zr[1].x + zr[3].x) + G1 * zr[2].x
            + SH * (Q_E * (lr0[1] + lr0[5]) + Q_D * (lr0[2] + lr0[4]) + Q_F * lr0[3]);
        o.y = G0 * (zr[1].y + zr[3].y) + G1 * zr[2].y
            + SH * (Q_E * (lr1[1] + lr1[5]) + Q_D * (lr1[2] + lr1[4]) + Q_F * lr1[3]);
        o1[PS2] = o;
        o.x = SH * (G0 * (hl0[1] + hl0[3]) + G1 * hl0[2]
            + Q_E * (hh0[0] + hh0[4]) + Q_D * (hh0[1] + hh0[3]) + Q_F * hh0[2]);
        o.y = SH * (G0 * (hl1[1] + hl1[3]) + G1 * hl1[2]
            + Q_E * (hh1[0] + hh1[4]) + Q_D * (hh1[1] + hh1[3]) + Q_F * hh1[2]);
        o2[0] = o;
        o.x = SH * (G0 * (hl0[2] + hl0[4]) + G1 * hl0[3]
            + Q_E * (hh0[1] + hh0[5]) + Q_D * (hh0[2] + hh0[4]) + Q_F * hh0[3]);
        o.y = SH * (G0 * (hl1[2] + hl1[4]) + G1 * hl1[3]
            + Q_E * (hh1[1] + hh1[5]) + Q_D * (hh1[2] + hh1[4]) + Q_F * hh1[3]);
        o2[PS2] = o;
    } else if (jp < chb) {
        kC_scalar<RI, CI>(z, yh, y1p, y2p, b, m, 2 * jp, 2 * jp + 4);
        kC_scalar<RI, CI>(z, yh, y1p, y2p, b, m, 2 * jp + 1, 2 * jp + 5);
    } else {
        int hp = jp - chb;
        int pc0 = (hp < 2) ? 2 * hp : (CI + 2 * hp);
#pragma unroll
        for (int s = 0; s < 2; s++) {
            int pc = pc0 + s;
            int jc = refl(pc - 4, CI);
            kC_scalar<RI, CI>(z, yh, y1p, y2p, b, m, jc, pc);
        }
    }
}

// ===========================================================================
// kD: branch-free final row filters. y1p,y2p:(128, R, C+10 padded) -> out.
// Thread = (row, p): float4 store at cols 4p..4p+3; 8 float2 loads total.
// ===========================================================================
template <int R, int C>
__global__ void __launch_bounds__(256)
kD(const float* __restrict__ y1p, const float* __restrict__ y2p,
   float* __restrict__ out) {
    constexpr int P = C / 4, PS2 = (C + 10) / 2;
    constexpr int LP = ilog2c(P);
    unsigned idx = blockIdx.x * 256u + threadIdx.x;
    int p = idx & (P - 1);
    int row = idx >> LP;  // b*R + i

    const float2* q1 = (const float2*)y1p + (size_t)row * PS2 + (2 * p + 1);
    const float2* q2 = (const float2*)y2p + (size_t)row * PS2 + (2 * p + 1);
    float2 f0 = __ldg(q1), f1 = __ldg(q1 + 1), f2 = __ldg(q1 + 2), f3 = __ldg(q1 + 3);
    float2 g0 = __ldg(q2), g1 = __ldg(q2 + 1), g2 = __ldg(q2 + 2), g3 = __ldg(q2 + 3);
    float a[6], v[8];
    a[0] = f0.y; a[1] = f1.x; a[2] = f1.y; a[3] = f2.x; a[4] = f2.y; a[5] = f3.x;
    v[0] = g0.x; v[1] = g0.y; v[2] = g1.x; v[3] = g1.y;
    v[4] = g2.x; v[5] = g2.y; v[6] = g3.x; v[7] = g3.y;
    float4 o;
    o.x = G0 * (a[0] + a[2]) + G1 * a[1] + Q_E * (v[0] + v[4]) + Q_D * (v[1] + v[3]) + Q_F * v[2];
    o.y = G0 * (a[1] + a[3]) + G1 * a[2] + Q_E * (v[1] + v[5]) + Q_D * (v[2] + v[4]) + Q_F * v[3];
    o.z = G0 * (a[2] + a[4]) + G1 * a[3] + Q_E * (v[2] + v[6]) + Q_D * (v[3] + v[5]) + Q_F * v[4];
    o.w = G0 * (a[3] + a[5]) + G1 * a[4] + Q_E * (v[3] + v[7]) + Q_D * (v[4] + v[6]) + Q_F * v[5];
    reinterpret_cast<float4*>(out + (size_t)row * C)[p] = o;
}

extern "C" void kernel_launch(void* const* d_in, const int* in_sizes, int n_in,
                              void* d_out, int out_size) {
    const float *yl = nullptr, *yh0 = nullptr, *yh1 = nullptr, *yh2 = nullptr;
    for (int i = 0; i < n_in; i++) {
        switch (in_sizes[i]) {
            case 524288:   yl  = (const float*)d_in[i]; break;  // 128*64*64
            case 25165824: yh0 = (const float*)d_in[i]; break;  // 128*6*128*128*2
            case 6291456:  yh1 = (const float*)d_in[i]; break;  // 128*6*64*64*2
            case 1572864:  yh2 = (const float*)d_in[i]; break;  // 128*6*32*32*2
            default: break;
        }
    }

    float *py1, *py2, *pz128, *pz256;
    cudaGetSymbolAddress((void**)&py1,   g_y1);
    cudaGetSymbolAddress((void**)&py2,   g_y2);
    cudaGetSymbolAddress((void**)&pz128, g_z128);
    cudaGetSymbolAddress((void**)&pz256, g_z256);

    // Level 1: (64,64) -> (128,128)
    kA<64, 64><<<128 * 32 * 37 / 256, 256>>>(yl, yh2, py1, py2);
    kB<128, 128><<<128 * 128 * 32 / 256, 256>>>(py1, py2, pz128);

    // Level 2: (128,128) -> (256,256)
    kA<128, 128><<<128 * 64 * 69 / 256, 256>>>(pz128, yh1, py1, py2);
    kB<256, 256><<<128 * 256 * 64 / 256, 256>>>(py1, py2, pz256);

    // Final level
    kC<256, 256><<<128 * 128 * 133 / 256, 256>>>(pz256, yh0, py1, py2);
    kD<256, 256><<<128 * 256 * 64 / 256, 256>>>(py1, py2, (float*)d_out);
}

// round 7
// speedup vs baseline: 1.4117x; 1.1568x over previous
#include <cuda_runtime.h>
#include <cuda_fp16.h>

// ---------------------------------------------------------------------------
// Inverse DTCWT, 3 levels. R6 structure (padded y buffers, branch-free row
// kernels) with all intermediates stored as fp16 (compute in fp32).
// Upsampling window index map (around 2n):
//   [0]=-4 [1]=-2 [2]=0 [3]=+2 [4]=-1 [5]=+1 [6]=+3 [7]=+5
// ---------------------------------------------------------------------------

#define SH   0.70710678118654752440f
#define C_A  0.23389032f
#define C_B  0.5875183f
#define C_C  0.11430184f
#define C_D  0.76027237f
#define C_E  0.08832942f
#define C_F  0.03516384f

#define G0   0.35355339059327f
#define G1   0.70710678118655f
#define Q_E  (-0.08838834764832f)
#define Q_D  (-0.17677669529664f)
#define Q_F  0.53033008588991f

#define LP0(L) ( C_A*L[1] + C_B*L[2] - C_C*L[3])
#define LP1(L) ( C_D*L[5] - C_E*L[6] + C_F*L[7])
#define LP2(L) ( C_F*L[0] - C_E*L[1] + C_D*L[2])
#define LP3(L) (-C_C*L[4] + C_B*L[5] + C_A*L[6])
#define HP0(H) (-C_D*H[5] + C_E*H[6] - C_F*H[7])
#define HP1(H) ( C_A*H[1] + C_B*H[2] - C_C*H[3])
#define HP2(H) (-C_C*H[4] + C_B*H[5] + C_A*H[6])
#define HP3(H) (-C_F*H[0] + C_E*H[1] - C_D*H[2])

// Scratch (fp16)
__device__ __half g_y1[128 * 256 * 268];
__device__ __half g_y2[128 * 256 * 268];
__device__ __half g_z128[128 * 128 * 128];
__device__ __half g_z256[128 * 256 * 256];

__device__ __forceinline__ int refl(int i, int n) {
    i = (i < 0) ? (-1 - i) : i;
    return (i >= n) ? (2 * n - 1 - i) : i;
}

__host__ __device__ constexpr int ilog2c(int v) { return v <= 1 ? 0 : 1 + ilog2c(v >> 1); }

__device__ __forceinline__ float  ld1(const float* p)   { return __ldg(p); }
__device__ __forceinline__ float  ld1(const __half* p)  { return __half2float(__ldg(p)); }
__device__ __forceinline__ float2 ld2(const float2* p)  { return __ldg(p); }
__device__ __forceinline__ float2 ld2(const __half2* p) { return __half22float2(__ldg(p)); }

template <typename T> struct vec2of;
template <> struct vec2of<float>  { using t = float2; };
template <> struct vec2of<__half> { using t = __half2; };

// ===========================================================================
// kA scalar path (any row n, any source column jc; writes padded col pc).
// ===========================================================================
template <int RI, int CI, typename TZ>
__device__ void kA_scalar(const TZ* __restrict__ z, const float* __restrict__ yh,
                          __half* __restrict__ y1p, __half* __restrict__ y2p,
                          int b, int n, int jc, int pc) {
    constexpr int rh = RI / 2, PS = CI + 12;
    const int d8[8] = {-4, -2, 0, 2, -1, 1, 3, 5};
    int pj = jc & 1;
    int rw[8], oB[8];
    float s1v[8], s2v[8];
#pragma unroll
    for (int t = 0; t < 8; t++) {
        int rr = refl(2 * n + d8[t], RI);
        rw[t] = rr;
        int ii = rr >> 1, pi = rr & 1;
        oB[t] = ii * CI + (pi ^ pj);
        s1v[t] = (pi & pj) ? -1.f : 1.f;
        s2v[t] = (pi & (pj ^ 1)) ? -1.f : 1.f;
    }
    const TZ* zb = z + (size_t)b * RI * CI + jc;
    const float* yb = yh + (size_t)b * 6 * rh * CI + 2 * (jc >> 1);
    const int sb = rh * CI;

    float L[8], H[8];
#pragma unroll
    for (int t = 0; t < 8; t++) L[t] = ld1(zb + rw[t] * CI);
#pragma unroll
    for (int t = 0; t < 8; t++)
        H[t] = s1v[t] * __ldg(yb + oB[t]) + s2v[t] * __ldg(yb + 5 * sb + oB[t]);  // lh

    __half* o1 = y1p + ((size_t)b * 2 * RI + 4 * n) * PS + pc;
    o1[0]      = __float2half(LP0(L) + SH * HP0(H));
    o1[PS]     = __float2half(LP1(L) + SH * HP1(H));
    o1[2 * PS] = __float2half(LP2(L) + SH * HP2(H));
    o1[3 * PS] = __float2half(LP3(L) + SH * HP3(H));

#pragma unroll
    for (int t = 0; t < 8; t++)
        L[t] = s1v[t] * __ldg(yb + 2 * sb + oB[t]) + s2v[t] * __ldg(yb + 3 * sb + oB[t]);  // hl
#pragma unroll
    for (int t = 0; t < 8; t++)
        H[t] = s1v[t] * __ldg(yb + 1 * sb + oB[t]) + s2v[t] * __ldg(yb + 4 * sb + oB[t]);  // hh

    __half* o2 = y2p + ((size_t)b * 2 * RI + 4 * n) * PS + pc;
    o2[0]      = __float2half(SH * (LP0(L) + HP0(H)));
    o2[PS]     = __float2half(SH * (LP1(L) + HP1(H)));
    o2[2 * PS] = __float2half(SH * (LP2(L) + HP2(H)));
    o2[3 * PS] = __float2half(SH * (LP3(L) + HP3(H)));
}

// ===========================================================================
// kA: column upsampling. z:(128,RI,CI) [TZ], yh:(128,6,RI/2,CI/2,2) [f32]
//  -> y1p,y2p:(128, 2*RI, CI+12) fp16, data at padded cols 4..CI+9.
// ===========================================================================
template <int RI, int CI, typename TZ>
__global__ void __launch_bounds__(256)
kA(const TZ* __restrict__ z, const float* __restrict__ yh,
   __half* __restrict__ y1p, __half* __restrict__ y2p) {
    constexpr int rh = RI / 2, ch = CI / 2, JP = ch + 5, PS = CI + 12, PS2 = PS / 2;
    using TZ2 = typename vec2of<TZ>::t;
    unsigned idx = blockIdx.x * 256u + threadIdx.x;
    int jp = idx % JP;
    int n = (idx / JP) % rh;
    int b = idx / (JP * rh);

    if (jp < ch && n >= 2 && n <= rh - 3) {
        const TZ2* z2 = (const TZ2*)z + (size_t)b * RI * ch + jp;
        const float2* yb2 = (const float2*)yh + (size_t)b * 6 * rh * ch + jp;
        const int sstr = rh * ch;
        int base = 2 * n;

        float2 Lz[8];
        Lz[0] = ld2(z2 + (base - 4) * ch);
        Lz[1] = ld2(z2 + (base - 2) * ch);
        Lz[2] = ld2(z2 + base * ch);
        Lz[3] = ld2(z2 + (base + 2) * ch);
        Lz[4] = ld2(z2 + (base - 1) * ch);
        Lz[5] = ld2(z2 + (base + 1) * ch);
        Lz[6] = ld2(z2 + (base + 3) * ch);
        Lz[7] = ld2(z2 + (base + 5) * ch);
        float L0[8], L1[8];
#pragma unroll
        for (int t = 0; t < 8; t++) { L0[t] = Lz[t].x; L1[t] = Lz[t].y; }

#define LOAD_PAIR5(S1, S2, B0, B1)                                            \
    {                                                                         \
        float2 w1[5], w2[5];                                                  \
        _Pragma("unroll") for (int t = 0; t < 5; t++) {                       \
            w1[t] = __ldg(yb2 + ((S1) * sstr + (n - 2 + t) * ch));            \
            w2[t] = __ldg(yb2 + ((S2) * sstr + (n - 2 + t) * ch));            \
        }                                                                     \
        _Pragma("unroll") for (int t = 0; t < 4; t++) {                       \
            B0[t] = w1[t].x + w2[t].x;                                        \
            B1[t] = w1[t].y + w2[t].y;                                        \
            B0[4 + t] = w1[t + 1].y - w2[t + 1].y;                            \
            B1[4 + t] = w2[t + 1].x - w1[t + 1].x;                            \
        }                                                                     \
    }
        __half2* o1 = (__half2*)y1p + ((size_t)b * 2 * RI + 4 * n) * PS2 + (jp + 2);
        {
            float B0[8], B1[8];
            LOAD_PAIR5(0, 5, B0, B1);  // lh
            o1[0]       = __floats2half2_rn(LP0(L0) + SH * HP0(B0), LP0(L1) + SH * HP0(B1));
            o1[PS2]     = __floats2half2_rn(LP1(L0) + SH * HP1(B0), LP1(L1) + SH * HP1(B1));
            o1[2 * PS2] = __floats2half2_rn(LP2(L0) + SH * HP2(B0), LP2(L1) + SH * HP2(B1));
            o1[3 * PS2] = __floats2half2_rn(LP3(L0) + SH * HP3(B0), LP3(L1) + SH * HP3(B1));
        }
        __half2* o2 = (__half2*)y2p + ((size_t)b * 2 * RI + 4 * n) * PS2 + (jp + 2);
        {
            float A0[8], A1[8], B0[8], B1[8];
            LOAD_PAIR5(2, 3, A0, A1);  // hl
            LOAD_PAIR5(1, 4, B0, B1);  // hh
            o2[0]       = __floats2half2_rn(SH * (LP0(A0) + HP0(B0)), SH * (LP0(A1) + HP0(B1)));
            o2[PS2]     = __floats2half2_rn(SH * (LP1(A0) + HP1(B0)), SH * (LP1(A1) + HP1(B1)));
            o2[2 * PS2] = __floats2half2_rn(SH * (LP2(A0) + HP2(B0)), SH * (LP2(A1) + HP2(B1)));
            o2[3 * PS2] = __floats2half2_rn(SH * (LP3(A0) + HP3(B0)), SH * (LP3(A1) + HP3(B1)));
        }
#undef LOAD_PAIR5
    } else if (jp < ch) {
        kA_scalar<RI, CI, TZ>(z, yh, y1p, y2p, b, n, 2 * jp, 2 * jp + 4);
        kA_scalar<RI, CI, TZ>(z, yh, y1p, y2p, b, n, 2 * jp + 1, 2 * jp + 5);
    } else {
        int hp = jp - ch;
        int pc0 = (hp < 2) ? 2 * hp : (CI + 2 * hp);
#pragma unroll
        for (int s = 0; s < 2; s++) {
            int pc = pc0 + s;
            int jc = refl(pc - 4, CI);
            kA_scalar<RI, CI, TZ>(z, yh, y1p, y2p, b, n, jc, pc);
        }
    }
}

// ===========================================================================
// kB: branch-free row upsampling. y1p,y2p fp16 padded -> Z fp16 (128,RO,CO).
// Thread = (row, n): 4 output cols, one 8-byte store.
// ===========================================================================
template <int RO, int CO>
__global__ void __launch_bounds__(256)
kB(const __half* __restrict__ y1p, const __half* __restrict__ y2p,
   __half* __restrict__ Z) {
    constexpr int ch = CO / 4;
    constexpr int PS2 = (CO / 2 + 12) / 2;  // half2 units
    constexpr int LCH = ilog2c(ch);
    unsigned idx = blockIdx.x * 256u + threadIdx.x;
    int n = idx & (ch - 1);
    int row = idx >> LCH;

    const __half2* q1 = (const __half2*)y1p + (size_t)row * PS2 + n;
    const __half2* q2 = (const __half2*)y2p + (size_t)row * PS2 + n;
    float2 u0 = ld2(q1), u1 = ld2(q1 + 1), u2 = ld2(q1 + 2),
           u3 = ld2(q1 + 3), u4 = ld2(q1 + 4);
    float2 w0 = ld2(q2), w1 = ld2(q2 + 1), w2 = ld2(q2 + 2),
           w3 = ld2(q2 + 3), w4 = ld2(q2 + 4);
    float L[8], H[8];
    L[0] = u0.x; L[1] = u1.x; L[2] = u2.x; L[3] = u3.x;
    L[4] = u1.y; L[5] = u2.y; L[6] = u3.y; L[7] = u4.y;
    H[0] = w0.x; H[1] = w1.x; H[2] = w2.x; H[3] = w3.x;
    H[4] = w1.y; H[5] = w2.y; H[6] = w3.y; H[7] = w4.y;

    __half2 ha = __floats2half2_rn(LP0(L) + HP0(H), LP1(L) + HP1(H));
    __half2 hb = __floats2half2_rn(LP2(L) + HP2(H), LP3(L) + HP3(H));
    uint2 pk;
    pk.x = *reinterpret_cast<const unsigned*>(&ha);
    pk.y = *reinterpret_cast<const unsigned*>(&hb);
    reinterpret_cast<uint2*>(Z + (size_t)row * CO)[n] = pk;
}

// ===========================================================================
// kC scalar path (final-level column filter).
// ===========================================================================
template <int RI, int CI>
__device__ void kC_scalar(const __half* __restrict__ z, const float* __restrict__ yh,
                          __half* __restrict__ y1p, __half* __restrict__ y2p,
                          int b, int m, int jc, int pc) {
    constexpr int rh = RI / 2, PS = CI + 10;
    int i0 = 2 * m;
    int pj = jc & 1;
    int o6[6];
    float s1v[6], s2v[6];
    int rr[6];
#pragma unroll
    for (int t = 0; t < 6; t++) {
        int rx = refl(i0 - 2 + t, RI);
        rr[t] = rx;
        int ii = rx >> 1, pi = rx & 1;
        o6[t] = ii * CI + (pi ^ pj);
        s1v[t] = (pi & pj) ? -1.f : 1.f;
        s2v[t] = (pi & (pj ^ 1)) ? -1.f : 1.f;
    }
    const __half* zb = z + (size_t)b * RI * CI + jc;
    const float* yb = yh + (size_t)b * 6 * rh * CI + 2 * (jc >> 1);
    const int sb = rh * CI;

    float zr[4];
#pragma unroll
    for (int t = 0; t < 4; t++) zr[t] = ld1(zb + rr[t + 1] * CI);

    float lr[6], hlr[6], hhr[6];
#pragma unroll
    for (int t = 0; t < 6; t++) {
        lr[t]  = s1v[t] * __ldg(yb + o6[t])          + s2v[t] * __ldg(yb + 5 * sb + o6[t]);
        hlr[t] = s1v[t] * __ldg(yb + 2 * sb + o6[t]) + s2v[t] * __ldg(yb + 3 * sb + o6[t]);
        hhr[t] = s1v[t] * __ldg(yb + 1 * sb + o6[t]) + s2v[t] * __ldg(yb + 4 * sb + o6[t]);
    }
    __half* o1 = y1p + ((size_t)b * RI + i0) * PS + pc;
    __half* o2 = y2p + ((size_t)b * RI + i0) * PS + pc;
    o1[0]  = __float2half(G0 * (zr[0] + zr[2]) + G1 * zr[1]
           + SH * (Q_E * (lr[0] + lr[4]) + Q_D * (lr[1] + lr[3]) + Q_F * lr[2]));
    o1[PS] = __float2half(G0 * (zr[1] + zr[3]) + G1 * zr[2]
           + SH * (Q_E * (lr[1] + lr[5]) + Q_D * (lr[2] + lr[4]) + Q_F * lr[3]));
    o2[0]  = __float2half(SH * (G0 * (hlr[1] + hlr[3]) + G1 * hlr[2]
           + Q_E * (hhr[0] + hhr[4]) + Q_D * (hhr[1] + hhr[3]) + Q_F * hhr[2]));
    o2[PS] = __float2half(SH * (G0 * (hlr[2] + hlr[4]) + G1 * hlr[3]
           + Q_E * (hhr[1] + hhr[5]) + Q_D * (hhr[2] + hhr[4]) + Q_F * hhr[3]));
}

// ===========================================================================
// kC: final-level column filters -> padded fp16 y1p,y2p (128, RI, CI+10).
// ===========================================================================
template <int RI, int CI>
__global__ void __launch_bounds__(256)
kC(const __half* __restrict__ z, const float* __restrict__ yh,
   __half* __restrict__ y1p, __half* __restrict__ y2p) {
    constexpr int rh = RI / 2, chb = CI / 2, JP = chb + 5, PS = CI + 10, PS2 = PS / 2;
    unsigned idx = blockIdx.x * 256u + threadIdx.x;
    int jp = idx % JP;
    int m = (idx / JP) % rh;
    int b = idx / (JP * rh);

    if (jp < chb && m >= 1 && m <= rh - 2) {
        int i0 = 2 * m;
        const __half2* z2 = (const __half2*)z + (size_t)b * RI * chb + jp;
        const float2* yb2 = (const float2*)yh + (size_t)b * 6 * rh * chb + jp;
        const int sstr = rh * chb;

        float2 zr[4];
#pragma unroll
        for (int t = 0; t < 4; t++) zr[t] = ld2(z2 + (i0 - 1 + t) * chb);

#define LOAD_PAIR3(S1, S2, B0, B1)                                            \
    {                                                                         \
        float2 w1[3], w2[3];                                                  \
        _Pragma("unroll") for (int t = 0; t < 3; t++) {                       \
            w1[t] = __ldg(yb2 + ((S1) * sstr + (m - 1 + t) * chb));           \
            w2[t] = __ldg(yb2 + ((S2) * sstr + (m - 1 + t) * chb));           \
        }                                                                     \
        _Pragma("unroll") for (int t = 0; t < 3; t++) {                       \
            B0[2 * t] = w1[t].x + w2[t].x;                                    \
            B1[2 * t] = w1[t].y + w2[t].y;                                    \
            B0[2 * t + 1] = w1[t].y - w2[t].y;                                \
            B1[2 * t + 1] = w2[t].x - w1[t].x;                                \
        }                                                                     \
    }
        float lr0[6], lr1[6], hl0[6], hl1[6], hh0[6], hh1[6];
        LOAD_PAIR3(0, 5, lr0, lr1);
        LOAD_PAIR3(2, 3, hl0, hl1);
        LOAD_PAIR3(1, 4, hh0, hh1);
#undef LOAD_PAIR3

        __half2* o1 = (__half2*)y1p + ((size_t)b * RI + i0) * PS2 + (jp + 2);
        __half2* o2 = (__half2*)y2p + ((size_t)b * RI + i0) * PS2 + (jp + 2);
        o1[0] = __floats2half2_rn(
            G0 * (zr[0].x + zr[2].x) + G1 * zr[1].x
          + SH * (Q_E * (lr0[0] + lr0[4]) + Q_D * (lr0[1] + lr0[3]) + Q_F * lr0[2]),
            G0 * (zr[0].y + zr[2].y) + G1 * zr[1].y
          + SH * (Q_E * (lr1[0] + lr1[4]) + Q_D * (lr1[1] + lr1[3]) + Q_F * lr1[2]));
        o1[PS2] = __floats2half2_rn(
            G0 * (zr[1].x + zr[3].x) + G1 * zr[2].x
          + SH * (Q_E * (lr0[1] + lr0[5]) + Q_D * (lr0[2] + lr0[4]) + Q_F * lr0[3]),
            G0 * (zr[1].y + zr[3].y) + G1 * zr[2].y
          + SH * (Q_E * (lr1[1] + lr1[5]) + Q_D * (lr1[2] + lr1[4]) + Q_F * lr1[3]));
        o2[0] = __floats2half2_rn(
            SH * (G0 * (hl0[1] + hl0[3]) + G1 * hl0[2]
          + Q_E * (hh0[0] + hh0[4]) + Q_D * (hh0[1] + hh0[3]) + Q_F * hh0[2]),
            SH * (G0 * (hl1[1] + hl1[3]) + G1 * hl1[2]
          + Q_E * (hh1[0] + hh1[4]) + Q_D * (hh1[1] + hh1[3]) + Q_F * hh1[2]));
        o2[PS2] = __floats2half2_rn(
            SH * (G0 * (hl0[2] + hl0[4]) + G1 * hl0[3]
          + Q_E * (hh0[1] + hh0[5]) + Q_D * (hh0[2] + hh0[4]) + Q_F * hh0[3]),
            SH * (G0 * (hl1[2] + hl1[4]) + G1 * hl1[3]
          + Q_E * (hh1[1] + hh1[5]) + Q_D * (hh1[2] + hh1[4]) + Q_F * hh1[3]));
    } else if (jp < chb) {
        kC_scalar<RI, CI>(z, yh, y1p, y2p, b, m, 2 * jp, 2 * jp + 4);
        kC_scalar<RI, CI>(z, yh, y1p, y2p, b, m, 2 * jp + 1, 2 * jp + 5);
    } else {
        int hp = jp - chb;
        int pc0 = (hp < 2) ? 2 * hp : (CI + 2 * hp);
#pragma unroll
        for (int s = 0; s < 2; s++) {
            int pc = pc0 + s;
            int jc = refl(pc - 4, CI);
            kC_scalar<RI, CI>(z, yh, y1p, y2p, b, m, jc, pc);
        }
    }
}

// ===========================================================================
// kD: branch-free final row filters. fp16 padded y1p,y2p -> fp32 out.
// ===========================================================================
template <int R, int C>
__global__ void __launch_bounds__(256)
kD(const __half* __restrict__ y1p, const __half* __restrict__ y2p,
   float* __restrict__ out) {
    constexpr int P = C / 4, PS2 = (C + 10) / 2;  // half2 units
    constexpr int LP = ilog2c(P);
    unsigned idx = blockIdx.x * 256u + threadIdx.x;
    int p = idx & (P - 1);
    int row = idx >> LP;

    const __half2* q1 = (const __half2*)y1p + (size_t)row * PS2 + (2 * p + 1);
    const __half2* q2 = (const __half2*)y2p + (size_t)row * PS2 + (2 * p + 1);
    float2 f0 = ld2(q1), f1 = ld2(q1 + 1), f2 = ld2(q1 + 2), f3 = ld2(q1 + 3);
    float2 g0 = ld2(q2), g1 = ld2(q2 + 1), g2 = ld2(q2 + 2), g3 = ld2(q2 + 3);
    float a[6], v[8];
    a[0] = f0.y; a[1] = f1.x; a[2] = f1.y; a[3] = f2.x; a[4] = f2.y; a[5] = f3.x;
    v[0] = g0.x; v[1] = g0.y; v[2] = g1.x; v[3] = g1.y;
    v[4] = g2.x; v[5] = g2.y; v[6] = g3.x; v[7] = g3.y;
    float4 o;
    o.x = G0 * (a[0] + a[2]) + G1 * a[1] + Q_E * (v[0] + v[4]) + Q_D * (v[1] + v[3]) + Q_F * v[2];
    o.y = G0 * (a[1] + a[3]) + G1 * a[2] + Q_E * (v[1] + v[5]) + Q_D * (v[2] + v[4]) + Q_F * v[3];
    o.z = G0 * (a[2] + a[4]) + G1 * a[3] + Q_E * (v[2] + v[6]) + Q_D * (v[3] + v[5]) + Q_F * v[4];
    o.w = G0 * (a[3] + a[5]) + G1 * a[4] + Q_E * (v[3] + v[7]) + Q_D * (v[4] + v[6]) + Q_F * v[5];
    reinterpret_cast<float4*>(out + (size_t)row * C)[p] = o;
}

extern "C" void kernel_launch(void* const* d_in, const int* in_sizes, int n_in,
                              void* d_out, int out_size) {
    const float *yl = nullptr, *yh0 = nullptr, *yh1 = nullptr, *yh2 = nullptr;
    for (int i = 0; i < n_in; i++) {
        switch (in_sizes[i]) {
            case 524288:   yl  = (const float*)d_in[i]; break;  // 128*64*64
            case 25165824: yh0 = (const float*)d_in[i]; break;  // 128*6*128*128*2
            case 6291456:  yh1 = (const float*)d_in[i]; break;  // 128*6*64*64*2
            case 1572864:  yh2 = (const float*)d_in[i]; break;  // 128*6*32*32*2
            default: break;
        }
    }

    __half *py1, *py2, *pz128, *pz256;
    cudaGetSymbolAddress((void**)&py1,   g_y1);
    cudaGetSymbolAddress((void**)&py2,   g_y2);
    cudaGetSymbolAddress((void**)&pz128, g_z128);
    cudaGetSymbolAddress((void**)&pz256, g_z256);

    // Level 1: (64,64) -> (128,128)
    kA<64, 64, float><<<128 * 32 * 37 / 256, 256>>>(yl, yh2, py1, py2);
    kB<128, 128><<<128 * 128 * 32 / 256, 256>>>(py1, py2, pz128);

    // Level 2: (128,128) -> (256,256)
    kA<128, 128, __half><<<128 * 64 * 69 / 256, 256>>>(pz128, yh1, py1, py2);
    kB<256, 256><<<128 * 256 * 64 / 256, 256>>>(py1, py2, pz256);

    // Final level
    kC<256, 256><<<128 * 128 * 133 / 256, 256>>>(pz256, yh0, py1, py2);
    kD<256, 256><<<128 * 256 * 64 / 256, 256>>>(py1, py2, (float*)d_out);
}

// round 8
// speedup vs baseline: 1.4840x; 1.0512x over previous
#include <cuda_runtime.h>
#include <cuda_fp16.h>

// ---------------------------------------------------------------------------
// Inverse DTCWT, 3 levels. fp16 intermediates (compute fp32), padded y
// buffers (reflection baked into halo cols), branch-free row kernels with
// 2 rows/thread, kC processes m-pairs (4 output rows) sharing band rows.
// ---------------------------------------------------------------------------

#define SH   0.70710678118654752440f
#define C_A  0.23389032f
#define C_B  0.5875183f
#define C_C  0.11430184f
#define C_D  0.76027237f
#define C_E  0.08832942f
#define C_F  0.03516384f

#define G0   0.35355339059327f
#define G1   0.70710678118655f
#define Q_E  (-0.08838834764832f)
#define Q_D  (-0.17677669529664f)
#define Q_F  0.53033008588991f

#define LP0(L) ( C_A*L[1] + C_B*L[2] - C_C*L[3])
#define LP1(L) ( C_D*L[5] - C_E*L[6] + C_F*L[7])
#define LP2(L) ( C_F*L[0] - C_E*L[1] + C_D*L[2])
#define LP3(L) (-C_C*L[4] + C_B*L[5] + C_A*L[6])
#define HP0(H) (-C_D*H[5] + C_E*H[6] - C_F*H[7])
#define HP1(H) ( C_A*H[1] + C_B*H[2] - C_C*H[3])
#define HP2(H) (-C_C*H[4] + C_B*H[5] + C_A*H[6])
#define HP3(H) (-C_F*H[0] + C_E*H[1] - C_D*H[2])

__device__ __half g_y1[128 * 256 * 268];
__device__ __half g_y2[128 * 256 * 268];
__device__ __half g_z128[128 * 128 * 128];
__device__ __half g_z256[128 * 256 * 256];

__device__ __forceinline__ int refl(int i, int n) {
    i = (i < 0) ? (-1 - i) : i;
    return (i >= n) ? (2 * n - 1 - i) : i;
}

__host__ __device__ constexpr int ilog2c(int v) { return v <= 1 ? 0 : 1 + ilog2c(v >> 1); }

__device__ __forceinline__ float  ld1(const float* p)   { return __ldg(p); }
__device__ __forceinline__ float  ld1(const __half* p)  { return __half2float(__ldg(p)); }
__device__ __forceinline__ float2 ld2(const float2* p)  { return __ldg(p); }
__device__ __forceinline__ float2 ld2(const __half2* p) { return __half22float2(__ldg(p)); }

template <typename T> struct vec2of;
template <> struct vec2of<float>  { using t = float2; };
template <> struct vec2of<__half> { using t = __half2; };

// ===========================================================================
// kA scalar path
// ===========================================================================
template <int RI, int CI, typename TZ>
__device__ void kA_scalar(const TZ* __restrict__ z, const float* __restrict__ yh,
                          __half* __restrict__ y1p, __half* __restrict__ y2p,
                          int b, int n, int jc, int pc) {
    constexpr int rh = RI / 2, PS = CI + 12;
    const int d8[8] = {-4, -2, 0, 2, -1, 1, 3, 5};
    int pj = jc & 1;
    int rw[8], oB[8];
    float s1v[8], s2v[8];
#pragma unroll
    for (int t = 0; t < 8; t++) {
        int rr = refl(2 * n + d8[t], RI);
        rw[t] = rr;
        int ii = rr >> 1, pi = rr & 1;
        oB[t] = ii * CI + (pi ^ pj);
        s1v[t] = (pi & pj) ? -1.f : 1.f;
        s2v[t] = (pi & (pj ^ 1)) ? -1.f : 1.f;
    }
    const TZ* zb = z + (size_t)b * RI * CI + jc;
    const float* yb = yh + (size_t)b * 6 * rh * CI + 2 * (jc >> 1);
    const int sb = rh * CI;

    float L[8], H[8];
#pragma unroll
    for (int t = 0; t < 8; t++) L[t] = ld1(zb + rw[t] * CI);
#pragma unroll
    for (int t = 0; t < 8; t++)
        H[t] = s1v[t] * __ldg(yb + oB[t]) + s2v[t] * __ldg(yb + 5 * sb + oB[t]);  // lh

    __half* o1 = y1p + ((size_t)b * 2 * RI + 4 * n) * PS + pc;
    o1[0]      = __float2half(LP0(L) + SH * HP0(H));
    o1[PS]     = __float2half(LP1(L) + SH * HP1(H));
    o1[2 * PS] = __float2half(LP2(L) + SH * HP2(H));
    o1[3 * PS] = __float2half(LP3(L) + SH * HP3(H));

#pragma unroll
    for (int t = 0; t < 8; t++)
        L[t] = s1v[t] * __ldg(yb + 2 * sb + oB[t]) + s2v[t] * __ldg(yb + 3 * sb + oB[t]);  // hl
#pragma unroll
    for (int t = 0; t < 8; t++)
        H[t] = s1v[t] * __ldg(yb + 1 * sb + oB[t]) + s2v[t] * __ldg(yb + 4 * sb + oB[t]);  // hh

    __half* o2 = y2p + ((size_t)b * 2 * RI + 4 * n) * PS + pc;
    o2[0]      = __float2half(SH * (LP0(L) + HP0(H)));
    o2[PS]     = __float2half(SH * (LP1(L) + HP1(H)));
    o2[2 * PS] = __float2half(SH * (LP2(L) + HP2(H)));
    o2[3 * PS] = __float2half(SH * (LP3(L) + HP3(H)));
}

// ===========================================================================
// kA: column upsampling (unchanged from R7).
// ===========================================================================
template <int RI, int CI, typename TZ>
__global__ void __launch_bounds__(256)
kA(const TZ* __restrict__ z, const float* __restrict__ yh,
   __half* __restrict__ y1p, __half* __restrict__ y2p) {
    constexpr int rh = RI / 2, ch = CI / 2, JP = ch + 5, PS = CI + 12, PS2 = PS / 2;
    using TZ2 = typename vec2of<TZ>::t;
    unsigned idx = blockIdx.x * 256u + threadIdx.x;
    int jp = idx % JP;
    int n = (idx / JP) % rh;
    int b = idx / (JP * rh);

    if (jp < ch && n >= 2 && n <= rh - 3) {
        const TZ2* z2 = (const TZ2*)z + (size_t)b * RI * ch + jp;
        const float2* yb2 = (const float2*)yh + (size_t)b * 6 * rh * ch + jp;
        const int sstr = rh * ch;
        int base = 2 * n;

        float2 Lz[8];
        Lz[0] = ld2(z2 + (base - 4) * ch);
        Lz[1] = ld2(z2 + (base - 2) * ch);
        Lz[2] = ld2(z2 + base * ch);
        Lz[3] = ld2(z2 + (base + 2) * ch);
        Lz[4] = ld2(z2 + (base - 1) * ch);
        Lz[5] = ld2(z2 + (base + 1) * ch);
        Lz[6] = ld2(z2 + (base + 3) * ch);
        Lz[7] = ld2(z2 + (base + 5) * ch);
        float L0[8], L1[8];
#pragma unroll
        for (int t = 0; t < 8; t++) { L0[t] = Lz[t].x; L1[t] = Lz[t].y; }

#define LOAD_PAIR5(S1, S2, B0, B1)                                            \
    {                                                                         \
        float2 w1[5], w2[5];                                                  \
        _Pragma("unroll") for (int t = 0; t < 5; t++) {                       \
            w1[t] = __ldg(yb2 + ((S1) * sstr + (n - 2 + t) * ch));            \
            w2[t] = __ldg(yb2 + ((S2) * sstr + (n - 2 + t) * ch));            \
        }                                                                     \
        _Pragma("unroll") for (int t = 0; t < 4; t++) {                       \
            B0[t] = w1[t].x + w2[t].x;                                        \
            B1[t] = w1[t].y + w2[t].y;                                        \
            B0[4 + t] = w1[t + 1].y - w2[t + 1].y;                            \
            B1[4 + t] = w2[t + 1].x - w1[t + 1].x;                            \
        }                                                                     \
    }
        __half2* o1 = (__half2*)y1p + ((size_t)b * 2 * RI + 4 * n) * PS2 + (jp + 2);
        {
            float B0[8], B1[8];
            LOAD_PAIR5(0, 5, B0, B1);  // lh
            o1[0]       = __floats2half2_rn(LP0(L0) + SH * HP0(B0), LP0(L1) + SH * HP0(B1));
            o1[PS2]     = __floats2half2_rn(LP1(L0) + SH * HP1(B0), LP1(L1) + SH * HP1(B1));
            o1[2 * PS2] = __floats2half2_rn(LP2(L0) + SH * HP2(B0), LP2(L1) + SH * HP2(B1));
            o1[3 * PS2] = __floats2half2_rn(LP3(L0) + SH * HP3(B0), LP3(L1) + SH * HP3(B1));
        }
        __half2* o2 = (__half2*)y2p + ((size_t)b * 2 * RI + 4 * n) * PS2 + (jp + 2);
        {
            float A0[8], A1[8], B0[8], B1[8];
            LOAD_PAIR5(2, 3, A0, A1);  // hl
            LOAD_PAIR5(1, 4, B0, B1);  // hh
            o2[0]       = __floats2half2_rn(SH * (LP0(A0) + HP0(B0)), SH * (LP0(A1) + HP0(B1)));
            o2[PS2]     = __floats2half2_rn(SH * (LP1(A0) + HP1(B0)), SH * (LP1(A1) + HP1(B1)));
            o2[2 * PS2] = __floats2half2_rn(SH * (LP2(A0) + HP2(B0)), SH * (LP2(A1) + HP2(B1)));
            o2[3 * PS2] = __floats2half2_rn(SH * (LP3(A0) + HP3(B0)), SH * (LP3(A1) + HP3(B1)));
        }
#undef LOAD_PAIR5
    } else if (jp < ch) {
        kA_scalar<RI, CI, TZ>(z, yh, y1p, y2p, b, n, 2 * jp, 2 * jp + 4);
        kA_scalar<RI, CI, TZ>(z, yh, y1p, y2p, b, n, 2 * jp + 1, 2 * jp + 5);
    } else {
        int hp = jp - ch;
        int pc0 = (hp < 2) ? 2 * hp : (CI + 2 * hp);
#pragma unroll
        for (int s = 0; s < 2; s++) {
            int pc = pc0 + s;
            int jc = refl(pc - 4, CI);
            kA_scalar<RI, CI, TZ>(z, yh, y1p, y2p, b, n, jc, pc);
        }
    }
}

// ===========================================================================
// kB: branch-free row upsampling, 2 rows per thread.
// ===========================================================================
template <int RO, int CO>
__global__ void __launch_bounds__(256)
kB(const __half* __restrict__ y1p, const __half* __restrict__ y2p,
   __half* __restrict__ Z) {
    constexpr int ch = CO / 4;
    constexpr int PS2 = (CO / 2 + 12) / 2;  // half2 units
    constexpr int LCH = ilog2c(ch);
    unsigned idx = blockIdx.x * 256u + threadIdx.x;
    int n = idx & (ch - 1);
    int rp = idx >> LCH;           // row pair
    int row0 = 2 * rp;

#pragma unroll
    for (int rr = 0; rr < 2; rr++) {
        int row = row0 + rr;
        const __half2* q1 = (const __half2*)y1p + (size_t)row * PS2 + n;
        const __half2* q2 = (const __half2*)y2p + (size_t)row * PS2 + n;
        float2 u0 = ld2(q1), u1 = ld2(q1 + 1), u2 = ld2(q1 + 2),
               u3 = ld2(q1 + 3), u4 = ld2(q1 + 4);
        float2 w0 = ld2(q2), w1 = ld2(q2 + 1), w2 = ld2(q2 + 2),
               w3 = ld2(q2 + 3), w4 = ld2(q2 + 4);
        float L[8], H[8];
        L[0] = u0.x; L[1] = u1.x; L[2] = u2.x; L[3] = u3.x;
        L[4] = u1.y; L[5] = u2.y; L[6] = u3.y; L[7] = u4.y;
        H[0] = w0.x; H[1] = w1.x; H[2] = w2.x; H[3] = w3.x;
        H[4] = w1.y; H[5] = w2.y; H[6] = w3.y; H[7] = w4.y;

        __half2 ha = __floats2half2_rn(LP0(L) + HP0(H), LP1(L) + HP1(H));
        __half2 hb = __floats2half2_rn(LP2(L) + HP2(H), LP3(L) + HP3(H));
        uint2 pk;
        pk.x = *reinterpret_cast<const unsigned*>(&ha);
        pk.y = *reinterpret_cast<const unsigned*>(&hb);
        reinterpret_cast<uint2*>(Z + (size_t)row * CO)[n] = pk;
    }
}

// ===========================================================================
// kC scalar path.
// ===========================================================================
template <int RI, int CI>
__device__ void kC_scalar(const __half* __restrict__ z, const float* __restrict__ yh,
                          __half* __restrict__ y1p, __half* __restrict__ y2p,
                          int b, int m, int jc, int pc) {
    constexpr int rh = RI / 2, PS = CI + 10;
    int i0 = 2 * m;
    int pj = jc & 1;
    int o6[6];
    float s1v[6], s2v[6];
    int rr[6];
#pragma unroll
    for (int t = 0; t < 6; t++) {
        int rx = refl(i0 - 2 + t, RI);
        rr[t] = rx;
        int ii = rx >> 1, pi = rx & 1;
        o6[t] = ii * CI + (pi ^ pj);
        s1v[t] = (pi & pj) ? -1.f : 1.f;
        s2v[t] = (pi & (pj ^ 1)) ? -1.f : 1.f;
    }
    const __half* zb = z + (size_t)b * RI * CI + jc;
    const float* yb = yh + (size_t)b * 6 * rh * CI + 2 * (jc >> 1);
    const int sb = rh * CI;

    float zr[4];
#pragma unroll
    for (int t = 0; t < 4; t++) zr[t] = ld1(zb + rr[t + 1] * CI);

    float lr[6], hlr[6], hhr[6];
#pragma unroll
    for (int t = 0; t < 6; t++) {
        lr[t]  = s1v[t] * __ldg(yb + o6[t])          + s2v[t] * __ldg(yb + 5 * sb + o6[t]);
        hlr[t] = s1v[t] * __ldg(yb + 2 * sb + o6[t]) + s2v[t] * __ldg(yb + 3 * sb + o6[t]);
        hhr[t] = s1v[t] * __ldg(yb + 1 * sb + o6[t]) + s2v[t] * __ldg(yb + 4 * sb + o6[t]);
    }
    __half* o1 = y1p + ((size_t)b * RI + i0) * PS + pc;
    __half* o2 = y2p + ((size_t)b * RI + i0) * PS + pc;
    o1[0]  = __float2half(G0 * (zr[0] + zr[2]) + G1 * zr[1]
           + SH * (Q_E * (lr[0] + lr[4]) + Q_D * (lr[1] + lr[3]) + Q_F * lr[2]));
    o1[PS] = __float2half(G0 * (zr[1] + zr[3]) + G1 * zr[2]
           + SH * (Q_E * (lr[1] + lr[5]) + Q_D * (lr[2] + lr[4]) + Q_F * lr[3]));
    o2[0]  = __float2half(SH * (G0 * (hlr[1] + hlr[3]) + G1 * hlr[2]
           + Q_E * (hhr[0] + hhr[4]) + Q_D * (hhr[1] + hhr[3]) + Q_F * hhr[2]));
    o2[PS] = __float2half(SH * (G0 * (hlr[2] + hlr[4]) + G1 * hlr[3]
           + Q_E * (hhr[1] + hhr[5]) + Q_D * (hhr[2] + hhr[4]) + Q_F * hhr[3]));
}

// ===========================================================================
// kC: final-level column filters, m-PAIR per thread (4 output rows).
// Band window rows mm-1..mm+2 shared between the two m's.
// ===========================================================================
template <int RI, int CI>
__global__ void __launch_bounds__(256)
kC(const __half* __restrict__ z, const float* __restrict__ yh,
   __half* __restrict__ y1p, __half* __restrict__ y2p) {
    constexpr int rh = RI / 2, chb = CI / 2, JP = chb + 5, PS = CI + 10, PS2 = PS / 2;
    constexpr int MP = rh / 2;
    unsigned idx = blockIdx.x * 256u + threadIdx.x;
    int jp = idx % JP;
    int mp = (idx / JP) % MP;
    int b = idx / (JP * MP);
    int mm = 2 * mp;

    if (jp < chb && mp >= 1 && mp <= MP - 2) {
        int i0 = 2 * mm;
        const __half2* z2 = (const __half2*)z + (size_t)b * RI * chb + jp;
        const float2* yb2 = (const float2*)yh + (size_t)b * 6 * rh * chb + jp;
        const int sstr = rh * chb;

        float2 zr[6];  // rows i0-1 .. i0+4
#pragma unroll
        for (int t = 0; t < 6; t++) zr[t] = ld2(z2 + (i0 - 1 + t) * chb);

        // W arrays span 8 window slots (4 subband rows, e/o interleaved).
#define LOAD_PAIR4(S1, S2, B0, B1)                                            \
    {                                                                         \
        float2 w1[4], w2[4];                                                  \
        _Pragma("unroll") for (int t = 0; t < 4; t++) {                       \
            w1[t] = __ldg(yb2 + ((S1) * sstr + (mm - 1 + t) * chb));          \
            w2[t] = __ldg(yb2 + ((S2) * sstr + (mm - 1 + t) * chb));          \
        }                                                                     \
        _Pragma("unroll") for (int t = 0; t < 4; t++) {                       \
            B0[2 * t] = w1[t].x + w2[t].x;                                    \
            B1[2 * t] = w1[t].y + w2[t].y;                                    \
            B0[2 * t + 1] = w1[t].y - w2[t].y;                                \
            B1[2 * t + 1] = w2[t].x - w1[t].x;                                \
        }                                                                     \
    }
        float lr0[8], lr1[8], hl0[8], hl1[8], hh0[8], hh1[8];
        LOAD_PAIR4(0, 5, lr0, lr1);
        LOAD_PAIR4(2, 3, hl0, hl1);
        LOAD_PAIR4(1, 4, hh0, hh1);
#undef LOAD_PAIR4

        __half2* o1 = (__half2*)y1p + ((size_t)b * RI + i0) * PS2 + (jp + 2);
        __half2* o2 = (__half2*)y2p + ((size_t)b * RI + i0) * PS2 + (jp + 2);
#pragma unroll
        for (int q = 0; q < 4; q += 2) {
            o1[q * PS2] = __floats2half2_rn(
                G0 * (zr[q + 0].x + zr[q + 2].x) + G1 * zr[q + 1].x
              + SH * (Q_E * (lr0[q + 0] + lr0[q + 4]) + Q_D * (lr0[q + 1] + lr0[q + 3]) + Q_F * lr0[q + 2]),
                G0 * (zr[q + 0].y + zr[q + 2].y) + G1 * zr[q + 1].y
              + SH * (Q_E * (lr1[q + 0] + lr1[q + 4]) + Q_D * (lr1[q + 1] + lr1[q + 3]) + Q_F * lr1[q + 2]));
            o1[(q + 1) * PS2] = __floats2half2_rn(
                G0 * (zr[q + 1].x + zr[q + 3].x) + G1 * zr[q + 2].x
              + SH * (Q_E * (lr0[q + 1] + lr0[q + 5]) + Q_D * (lr0[q + 2] + lr0[q + 4]) + Q_F * lr0[q + 3]),
                G0 * (zr[q + 1].y + zr[q + 3].y) + G1 * zr[q + 2].y
              + SH * (Q_E * (lr1[q + 1] + lr1[q + 5]) + Q_D * (lr1[q + 2] + lr1[q + 4]) + Q_F * lr1[q + 3]));
            o2[q * PS2] = __floats2half2_rn(
                SH * (G0 * (hl0[q + 1] + hl0[q + 3]) + G1 * hl0[q + 2]
              + Q_E * (hh0[q + 0] + hh0[q + 4]) + Q_D * (hh0[q + 1] + hh0[q + 3]) + Q_F * hh0[q + 2]),
                SH * (G0 * (hl1[q + 1] + hl1[q + 3]) + G1 * hl1[q + 2]
              + Q_E * (hh1[q + 0] + hh1[q + 4]) + Q_D * (hh1[q + 1] + hh1[q + 3]) + Q_F * hh1[q + 2]));
            o2[(q + 1) * PS2] = __floats2half2_rn(
                SH * (G0 * (hl0[q + 2] + hl0[q + 4]) + G1 * hl0[q + 3]
              + Q_E * (hh0[q + 1] + hh0[q + 5]) + Q_D * (hh0[q + 2] + hh0[q + 4]) + Q_F * hh0[q + 3]),
                SH * (G0 * (hl1[q + 2] + hl1[q + 4]) + G1 * hl1[q + 3]
              + Q_E * (hh1[q + 1] + hh1[q + 5]) + Q_D * (hh1[q + 2] + hh1[q + 4]) + Q_F * hh1[q + 3]));
        }
    } else if (jp < chb) {
#pragma unroll
        for (int dm = 0; dm < 2; dm++) {
            kC_scalar<RI, CI>(z, yh, y1p, y2p, b, mm + dm, 2 * jp, 2 * jp + 4);
            kC_scalar<RI, CI>(z, yh, y1p, y2p, b, mm + dm, 2 * jp + 1, 2 * jp + 5);
        }
    } else {
        int hp = jp - chb;
        int pc0 = (hp < 2) ? 2 * hp : (CI + 2 * hp);
#pragma unroll
        for (int dm = 0; dm < 2; dm++) {
#pragma unroll
            for (int s = 0; s < 2; s++) {
                int pc = pc0 + s;
                int jc = refl(pc - 4, CI);
                kC_scalar<RI, CI>(z, yh, y1p, y2p, b, mm + dm, jc, pc);
            }
        }
    }
}

// ===========================================================================
// kD: branch-free final row filters, 2 rows per thread. fp16 -> fp32 out.
// ===========================================================================
template <int R, int C>
__global__ void __launch_bounds__(256)
kD(const __half* __restrict__ y1p, const __half* __restrict__ y2p,
   float* __restrict__ out) {
    constexpr int P = C / 4, PS2 = (C + 10) / 2;
    constexpr int LP = ilog2c(P);
    unsigned idx = blockIdx.x * 256u + threadIdx.x;
    int p = idx & (P - 1);
    int rp = idx >> LP;
    int row0 = 2 * rp;

#pragma unroll
    for (int rr = 0; rr < 2; rr++) {
        int row = row0 + rr;
        const __half2* q1 = (const __half2*)y1p + (size_t)row * PS2 + (2 * p + 1);
        const __half2* q2 = (const __half2*)y2p + (size_t)row * PS2 + (2 * p + 1);
        float2 f0 = ld2(q1), f1 = ld2(q1 + 1), f2 = ld2(q1 + 2), f3 = ld2(q1 + 3);
        float2 g0 = ld2(q2), g1 = ld2(q2 + 1), g2 = ld2(q2 + 2), g3 = ld2(q2 + 3);
        float a[6], v[8];
        a[0] = f0.y; a[1] = f1.x; a[2] = f1.y; a[3] = f2.x; a[4] = f2.y; a[5] = f3.x;
        v[0] = g0.x; v[1] = g0.y; v[2] = g1.x; v[3] = g1.y;
        v[4] = g2.x; v[5] = g2.y; v[6] = g3.x; v[7] = g3.y;
        float4 o;
        o.x = G0 * (a[0] + a[2]) + G1 * a[1] + Q_E * (v[0] + v[4]) + Q_D * (v[1] + v[3]) + Q_F * v[2];
        o.y = G0 * (a[1] + a[3]) + G1 * a[2] + Q_E * (v[1] + v[5]) + Q_D * (v[2] + v[4]) + Q_F * v[3];
        o.z = G0 * (a[2] + a[4]) + G1 * a[3] + Q_E * (v[2] + v[6]) + Q_D * (v[3] + v[5]) + Q_F * v[4];
        o.w = G0 * (a[3] + a[5]) + G1 * a[4] + Q_E * (v[3] + v[7]) + Q_D * (v[4] + v[6]) + Q_F * v[5];
        reinterpret_cast<float4*>(out + (size_t)row * C)[p] = o;
    }
}

extern "C" void kernel_launch(void* const* d_in, const int* in_sizes, int n_in,
                              void* d_out, int out_size) {
    const float *yl = nullptr, *yh0 = nullptr, *yh1 = nullptr, *yh2 = nullptr;
    for (int i = 0; i < n_in; i++) {
        switch (in_sizes[i]) {
            case 524288:   yl  = (const float*)d_in[i]; break;  // 128*64*64
            case 25165824: yh0 = (const float*)d_in[i]; break;  // 128*6*128*128*2
            case 6291456:  yh1 = (const float*)d_in[i]; break;  // 128*6*64*64*2
            case 1572864:  yh2 = (const float*)d_in[i]; break;  // 128*6*32*32*2
            default: break;
        }
    }

    __half *py1, *py2, *pz128, *pz256;
    cudaGetSymbolAddress((void**)&py1,   g_y1);
    cudaGetSymbolAddress((void**)&py2,   g_y2);
    cudaGetSymbolAddress((void**)&pz128, g_z128);
    cudaGetSymbolAddress((void**)&pz256, g_z256);

    // Level 1: (64,64) -> (128,128)
    kA<64, 64, float><<<128 * 32 * 37 / 256, 256>>>(yl, yh2, py1, py2);
    kB<128, 128><<<128 * 64 * 32 / 256, 256>>>(py1, py2, pz128);

    // Level 2: (128,128) -> (256,256)
    kA<128, 128, __half><<<128 * 64 * 69 / 256, 256>>>(pz128, yh1, py1, py2);
    kB<256, 256><<<128 * 128 * 64 / 256, 256>>>(py1, py2, pz256);

    // Final level
    kC<256, 256><<<128 * 64 * 133 / 256, 256>>>(pz256, yh0, py1, py2);
    kD<256, 256><<<128 * 128 * 64 / 256, 256>>>(py1, py2, (float*)d_out);
}

// round 9
// speedup vs baseline: 1.5481x; 1.0432x over previous
#include <cuda_runtime.h>
#include <cuda_fp16.h>

// ---------------------------------------------------------------------------
// Inverse DTCWT, 3 levels. fp16 intermediates, padded + INTERLEAVED y buffer:
// element (row, c2) = uint2 { y1 half2, y2 half2 }. Row kernels branch-free.
// ---------------------------------------------------------------------------

#define SH   0.70710678118654752440f
#define C_A  0.23389032f
#define C_B  0.5875183f
#define C_C  0.11430184f
#define C_D  0.76027237f
#define C_E  0.08832942f
#define C_F  0.03516384f

#define G0   0.35355339059327f
#define G1   0.70710678118655f
#define Q_E  (-0.08838834764832f)
#define Q_D  (-0.17677669529664f)
#define Q_F  0.53033008588991f

#define LP0(L) ( C_A*L[1] + C_B*L[2] - C_C*L[3])
#define LP1(L) ( C_D*L[5] - C_E*L[6] + C_F*L[7])
#define LP2(L) ( C_F*L[0] - C_E*L[1] + C_D*L[2])
#define LP3(L) (-C_C*L[4] + C_B*L[5] + C_A*L[6])
#define HP0(H) (-C_D*H[5] + C_E*H[6] - C_F*H[7])
#define HP1(H) ( C_A*H[1] + C_B*H[2] - C_C*H[3])
#define HP2(H) (-C_C*H[4] + C_B*H[5] + C_A*H[6])
#define HP3(H) (-C_F*H[0] + C_E*H[1] - C_D*H[2])

// Interleaved padded y buffer: uint2 = {y1 half2, y2 half2}
__device__ uint2  g_yp[128 * 256 * 134];
__device__ __half g_z128[128 * 128 * 128];
__device__ __half g_z256[128 * 256 * 256];

__device__ __forceinline__ int refl(int i, int n) {
    i = (i < 0) ? (-1 - i) : i;
    return (i >= n) ? (2 * n - 1 - i) : i;
}

__host__ __device__ constexpr int ilog2c(int v) { return v <= 1 ? 0 : 1 + ilog2c(v >> 1); }

__device__ __forceinline__ float  ld1(const float* p)   { return __ldg(p); }
__device__ __forceinline__ float  ld1(const __half* p)  { return __half2float(__ldg(p)); }
__device__ __forceinline__ float2 ld2(const float2* p)  { return __ldg(p); }
__device__ __forceinline__ float2 ld2(const __half2* p) { return __half22float2(__ldg(p)); }

__device__ __forceinline__ uint2 pack2(__half2 a, __half2 b) {
    uint2 r;
    r.x = *reinterpret_cast<const unsigned*>(&a);
    r.y = *reinterpret_cast<const unsigned*>(&b);
    return r;
}
__device__ __forceinline__ float2 unpk_lo(uint2 v) {
    __half2 h = *reinterpret_cast<const __half2*>(&v.x);
    return __half22float2(h);
}
__device__ __forceinline__ float2 unpk_hi(uint2 v) {
    __half2 h = *reinterpret_cast<const __half2*>(&v.y);
    return __half22float2(h);
}

template <typename T> struct vec2of;
template <> struct vec2of<float>  { using t = float2; };
template <> struct vec2of<__half> { using t = __half2; };

// ===========================================================================
// kA scalar path: writes single halves into interleaved layout.
// ===========================================================================
template <int RI, int CI, typename TZ>
__device__ void kA_scalar(const TZ* __restrict__ z, const float* __restrict__ yh,
                          uint2* __restrict__ yp, int b, int n, int jc, int pc) {
    constexpr int rh = RI / 2, PS2 = (CI + 12) / 2;
    const int d8[8] = {-4, -2, 0, 2, -1, 1, 3, 5};
    int pj = jc & 1;
    int rw[8], oB[8];
    float s1v[8], s2v[8];
#pragma unroll
    for (int t = 0; t < 8; t++) {
        int rr = refl(2 * n + d8[t], RI);
        rw[t] = rr;
        int ii = rr >> 1, pi = rr & 1;
        oB[t] = ii * CI + (pi ^ pj);
        s1v[t] = (pi & pj) ? -1.f : 1.f;
        s2v[t] = (pi & (pj ^ 1)) ? -1.f : 1.f;
    }
    const TZ* zb = z + (size_t)b * RI * CI + jc;
    const float* yb = yh + (size_t)b * 6 * rh * CI + 2 * (jc >> 1);
    const int sb = rh * CI;

    float L[8], H[8], A[8], B[8];
#pragma unroll
    for (int t = 0; t < 8; t++) L[t] = ld1(zb + rw[t] * CI);
#pragma unroll
    for (int t = 0; t < 8; t++) {
        H[t] = s1v[t] * __ldg(yb + oB[t]) + s2v[t] * __ldg(yb + 5 * sb + oB[t]);          // lh
        A[t] = s1v[t] * __ldg(yb + 2 * sb + oB[t]) + s2v[t] * __ldg(yb + 3 * sb + oB[t]); // hl
        B[t] = s1v[t] * __ldg(yb + 1 * sb + oB[t]) + s2v[t] * __ldg(yb + 4 * sb + oB[t]); // hh
    }

    // half-granular address into interleaved buffer
    __half* o = (__half*)yp + (((size_t)b * 2 * RI + 4 * n) * PS2 + (pc >> 1)) * 4 + (pc & 1);
    const int rs = PS2 * 4;
    o[0]          = __float2half(LP0(L) + SH * HP0(H));
    o[2]          = __float2half(SH * (LP0(A) + HP0(B)));
    o[rs]         = __float2half(LP1(L) + SH * HP1(H));
    o[rs + 2]     = __float2half(SH * (LP1(A) + HP1(B)));
    o[2 * rs]     = __float2half(LP2(L) + SH * HP2(H));
    o[2 * rs + 2] = __float2half(SH * (LP2(A) + HP2(B)));
    o[3 * rs]     = __float2half(LP3(L) + SH * HP3(H));
    o[3 * rs + 2] = __float2half(SH * (LP3(A) + HP3(B)));
}

// ===========================================================================
// kA: column upsampling -> interleaved padded buffer, cols 4..CI+9.
// ===========================================================================
template <int RI, int CI, typename TZ>
__global__ void __launch_bounds__(256)
kA(const TZ* __restrict__ z, const float* __restrict__ yh,
   uint2* __restrict__ yp) {
    constexpr int rh = RI / 2, ch = CI / 2, JP = ch + 5, PS2 = (CI + 12) / 2;
    using TZ2 = typename vec2of<TZ>::t;
    unsigned idx = blockIdx.x * 256u + threadIdx.x;
    int jp = idx % JP;
    int n = (idx / JP) % rh;
    int b = idx / (JP * rh);

    if (jp < ch && n >= 2 && n <= rh - 3) {
        const TZ2* z2 = (const TZ2*)z + (size_t)b * RI * ch + jp;
        const float2* yb2 = (const float2*)yh + (size_t)b * 6 * rh * ch + jp;
        const int sstr = rh * ch;
        int base = 2 * n;

        float2 Lz[8];
        Lz[0] = ld2(z2 + (base - 4) * ch);
        Lz[1] = ld2(z2 + (base - 2) * ch);
        Lz[2] = ld2(z2 + base * ch);
        Lz[3] = ld2(z2 + (base + 2) * ch);
        Lz[4] = ld2(z2 + (base - 1) * ch);
        Lz[5] = ld2(z2 + (base + 1) * ch);
        Lz[6] = ld2(z2 + (base + 3) * ch);
        Lz[7] = ld2(z2 + (base + 5) * ch);
        float L0[8], L1[8];
#pragma unroll
        for (int t = 0; t < 8; t++) { L0[t] = Lz[t].x; L1[t] = Lz[t].y; }

#define LOAD_PAIR5(S1, S2, B0, B1)                                            \
    {                                                                         \
        float2 w1[5], w2[5];                                                  \
        _Pragma("unroll") for (int t = 0; t < 5; t++) {                       \
            w1[t] = __ldg(yb2 + ((S1) * sstr + (n - 2 + t) * ch));            \
            w2[t] = __ldg(yb2 + ((S2) * sstr + (n - 2 + t) * ch));            \
        }                                                                     \
        _Pragma("unroll") for (int t = 0; t < 4; t++) {                       \
            B0[t] = w1[t].x + w2[t].x;                                        \
            B1[t] = w1[t].y + w2[t].y;                                        \
            B0[4 + t] = w1[t + 1].y - w2[t + 1].y;                            \
            B1[4 + t] = w2[t + 1].x - w1[t + 1].x;                            \
        }                                                                     \
    }
        float H0[8], H1[8], A0[8], A1[8], B0[8], B1[8];
        LOAD_PAIR5(0, 5, H0, H1);  // lh
        LOAD_PAIR5(2, 3, A0, A1);  // hl
        LOAD_PAIR5(1, 4, B0, B1);  // hh
#undef LOAD_PAIR5

        uint2* o = yp + ((size_t)b * 2 * RI + 4 * n) * PS2 + (jp + 2);
        o[0] = pack2(__floats2half2_rn(LP0(L0) + SH * HP0(H0), LP0(L1) + SH * HP0(H1)),
                     __floats2half2_rn(SH * (LP0(A0) + HP0(B0)), SH * (LP0(A1) + HP0(B1))));
        o[PS2] = pack2(__floats2half2_rn(LP1(L0) + SH * HP1(H0), LP1(L1) + SH * HP1(H1)),
                       __floats2half2_rn(SH * (LP1(A0) + HP1(B0)), SH * (LP1(A1) + HP1(B1))));
        o[2 * PS2] = pack2(__floats2half2_rn(LP2(L0) + SH * HP2(H0), LP2(L1) + SH * HP2(H1)),
                           __floats2half2_rn(SH * (LP2(A0) + HP2(B0)), SH * (LP2(A1) + HP2(B1))));
        o[3 * PS2] = pack2(__floats2half2_rn(LP3(L0) + SH * HP3(H0), LP3(L1) + SH * HP3(H1)),
                           __floats2half2_rn(SH * (LP3(A0) + HP3(B0)), SH * (LP3(A1) + HP3(B1))));
    } else if (jp < ch) {
        kA_scalar<RI, CI, TZ>(z, yh, yp, b, n, 2 * jp, 2 * jp + 4);
        kA_scalar<RI, CI, TZ>(z, yh, yp, b, n, 2 * jp + 1, 2 * jp + 5);
    } else {
        int hp = jp - ch;
        int pc0 = (hp < 2) ? 2 * hp : (CI + 2 * hp);
#pragma unroll
        for (int s = 0; s < 2; s++) {
            int pc = pc0 + s;
            int jc = refl(pc - 4, CI);
            kA_scalar<RI, CI, TZ>(z, yh, yp, b, n, jc, pc);
        }
    }
}

// ===========================================================================
// kB: branch-free row upsampling, 2 rows/thread, 5 uint2 loads per row.
// ===========================================================================
template <int RO, int CO>
__global__ void __launch_bounds__(256)
kB(const uint2* __restrict__ yp, __half* __restrict__ Z) {
    constexpr int ch = CO / 4;
    constexpr int PS2 = (CO / 2 + 12) / 2;
    constexpr int LCH = ilog2c(ch);
    unsigned idx = blockIdx.x * 256u + threadIdx.x;
    int n = idx & (ch - 1);
    int rp = idx >> LCH;
    int row0 = 2 * rp;

#pragma unroll
    for (int rr = 0; rr < 2; rr++) {
        int row = row0 + rr;
        const uint2* q = yp + (size_t)row * PS2 + n;
        uint2 v0 = __ldg(q), v1 = __ldg(q + 1), v2 = __ldg(q + 2),
              v3 = __ldg(q + 3), v4 = __ldg(q + 4);
        float2 u0 = unpk_lo(v0), u1 = unpk_lo(v1), u2 = unpk_lo(v2),
               u3 = unpk_lo(v3), u4 = unpk_lo(v4);
        float2 w0 = unpk_hi(v0), w1 = unpk_hi(v1), w2 = unpk_hi(v2),
               w3 = unpk_hi(v3), w4 = unpk_hi(v4);
        float L[8], H[8];
        L[0] = u0.x; L[1] = u1.x; L[2] = u2.x; L[3] = u3.x;
        L[4] = u1.y; L[5] = u2.y; L[6] = u3.y; L[7] = u4.y;
        H[0] = w0.x; H[1] = w1.x; H[2] = w2.x; H[3] = w3.x;
        H[4] = w1.y; H[5] = w2.y; H[6] = w3.y; H[7] = w4.y;

        __half2 ha = __floats2half2_rn(LP0(L) + HP0(H), LP1(L) + HP1(H));
        __half2 hb = __floats2half2_rn(LP2(L) + HP2(H), LP3(L) + HP3(H));
        reinterpret_cast<uint2*>(Z + (size_t)row * CO)[n] = pack2(ha, hb);
    }
}

// ===========================================================================
// kC scalar path.
// ===========================================================================
template <int RI, int CI>
__device__ void kC_scalar(const __half* __restrict__ z, const float* __restrict__ yh,
                          uint2* __restrict__ yp, int b, int m, int jc, int pc) {
    constexpr int rh = RI / 2, PS2 = (CI + 10) / 2;
    int i0 = 2 * m;
    int pj = jc & 1;
    int o6[6];
    float s1v[6], s2v[6];
    int rr[6];
#pragma unroll
    for (int t = 0; t < 6; t++) {
        int rx = refl(i0 - 2 + t, RI);
        rr[t] = rx;
        int ii = rx >> 1, pi = rx & 1;
        o6[t] = ii * CI + (pi ^ pj);
        s1v[t] = (pi & pj) ? -1.f : 1.f;
        s2v[t] = (pi & (pj ^ 1)) ? -1.f : 1.f;
    }
    const __half* zb = z + (size_t)b * RI * CI + jc;
    const float* yb = yh + (size_t)b * 6 * rh * CI + 2 * (jc >> 1);
    const int sb = rh * CI;

    float zr[4];
#pragma unroll
    for (int t = 0; t < 4; t++) zr[t] = ld1(zb + rr[t + 1] * CI);

    float lr[6], hlr[6], hhr[6];
#pragma unroll
    for (int t = 0; t < 6; t++) {
        lr[t]  = s1v[t] * __ldg(yb + o6[t])          + s2v[t] * __ldg(yb + 5 * sb + o6[t]);
        hlr[t] = s1v[t] * __ldg(yb + 2 * sb + o6[t]) + s2v[t] * __ldg(yb + 3 * sb + o6[t]);
        hhr[t] = s1v[t] * __ldg(yb + 1 * sb + o6[t]) + s2v[t] * __ldg(yb + 4 * sb + o6[t]);
    }
    __half* o = (__half*)yp + (((size_t)b * RI + i0) * PS2 + (pc >> 1)) * 4 + (pc & 1);
    const int rs = PS2 * 4;
    o[0]      = __float2half(G0 * (zr[0] + zr[2]) + G1 * zr[1]
              + SH * (Q_E * (lr[0] + lr[4]) + Q_D * (lr[1] + lr[3]) + Q_F * lr[2]));
    o[rs]     = __float2half(G0 * (zr[1] + zr[3]) + G1 * zr[2]
              + SH * (Q_E * (lr[1] + lr[5]) + Q_D * (lr[2] + lr[4]) + Q_F * lr[3]));
    o[2]      = __float2half(SH * (G0 * (hlr[1] + hlr[3]) + G1 * hlr[2]
              + Q_E * (hhr[0] + hhr[4]) + Q_D * (hhr[1] + hhr[3]) + Q_F * hhr[2]));
    o[rs + 2] = __float2half(SH * (G0 * (hlr[2] + hlr[4]) + G1 * hlr[3]
              + Q_E * (hhr[1] + hhr[5]) + Q_D * (hhr[2] + hhr[4]) + Q_F * hhr[3]));
}

// ===========================================================================
// kC: final-level column filters, m-pair per thread (4 output rows).
// ===========================================================================
template <int RI, int CI>
__global__ void __launch_bounds__(256)
kC(const __half* __restrict__ z, const float* __restrict__ yh,
   uint2* __restrict__ yp) {
    constexpr int rh = RI / 2, chb = CI / 2, JP = chb + 5, PS2 = (CI + 10) / 2;
    constexpr int MP = rh / 2;
    unsigned idx = blockIdx.x * 256u + threadIdx.x;
    int jp = idx % JP;
    int mp = (idx / JP) % MP;
    int b = idx / (JP * MP);
    int mm = 2 * mp;

    if (jp < chb && mp >= 1 && mp <= MP - 2) {
        int i0 = 2 * mm;
        const __half2* z2 = (const __half2*)z + (size_t)b * RI * chb + jp;
        const float2* yb2 = (const float2*)yh + (size_t)b * 6 * rh * chb + jp;
        const int sstr = rh * chb;

        float2 zr[6];
#pragma unroll
        for (int t = 0; t < 6; t++) zr[t] = ld2(z2 + (i0 - 1 + t) * chb);

#define LOAD_PAIR4(S1, S2, B0, B1)                                            \
    {                                                                         \
        float2 w1[4], w2[4];                                                  \
        _Pragma("unroll") for (int t = 0; t < 4; t++) {                       \
            w1[t] = __ldg(yb2 + ((S1) * sstr + (mm - 1 + t) * chb));          \
            w2[t] = __ldg(yb2 + ((S2) * sstr + (mm - 1 + t) * chb));          \
        }                                                                     \
        _Pragma("unroll") for (int t = 0; t < 4; t++) {                       \
            B0[2 * t] = w1[t].x + w2[t].x;                                    \
            B1[2 * t] = w1[t].y + w2[t].y;                                    \
            B0[2 * t + 1] = w1[t].y - w2[t].y;                                \
            B1[2 * t + 1] = w2[t].x - w1[t].x;                                \
        }                                                                     \
    }
        float lr0[8], lr1[8], hl0[8], hl1[8], hh0[8], hh1[8];
        LOAD_PAIR4(0, 5, lr0, lr1);
        LOAD_PAIR4(2, 3, hl0, hl1);
        LOAD_PAIR4(1, 4, hh0, hh1);
#undef LOAD_PAIR4

        uint2* o = yp + ((size_t)b * RI + i0) * PS2 + (jp + 2);
#pragma unroll
        for (int q = 0; q < 4; q++) {
            __half2 h1 = __floats2half2_rn(
                G0 * (zr[q].x + zr[q + 2].x) + G1 * zr[q + 1].x
              + SH * (Q_E * (lr0[q] + lr0[q + 4]) + Q_D * (lr0[q + 1] + lr0[q + 3]) + Q_F * lr0[q + 2]),
                G0 * (zr[q].y + zr[q + 2].y) + G1 * zr[q + 1].y
              + SH * (Q_E * (lr1[q] + lr1[q + 4]) + Q_D * (lr1[q + 1] + lr1[q + 3]) + Q_F * lr1[q + 2]));
            __half2 h2 = __floats2half2_rn(
                SH * (G0 * (hl0[q + 1] + hl0[q + 3]) + G1 * hl0[q + 2]
              + Q_E * (hh0[q] + hh0[q + 4]) + Q_D * (hh0[q + 1] + hh0[q + 3]) + Q_F * hh0[q + 2]),
                SH * (G0 * (hl1[q + 1] + hl1[q + 3]) + G1 * hl1[q + 2]
              + Q_E * (hh1[q] + hh1[q + 4]) + Q_D * (hh1[q + 1] + hh1[q + 3]) + Q_F * hh1[q + 2]));
            o[q * PS2] = pack2(h1, h2);
        }
    } else if (jp < chb) {
#pragma unroll
        for (int dm = 0; dm < 2; dm++) {
            kC_scalar<RI, CI>(z, yh, yp, b, mm + dm, 2 * jp, 2 * jp + 4);
            kC_scalar<RI, CI>(z, yh, yp, b, mm + dm, 2 * jp + 1, 2 * jp + 5);
        }
    } else {
        int hp = jp - chb;
        int pc0 = (hp < 2) ? 2 * hp : (CI + 2 * hp);
#pragma unroll
        for (int dm = 0; dm < 2; dm++) {
#pragma unroll
            for (int s = 0; s < 2; s++) {
                int pc = pc0 + s;
                int jc = refl(pc - 4, CI);
                kC_scalar<RI, CI>(z, yh, yp, b, mm + dm, jc, pc);
            }
        }
    }
}

// ===========================================================================
// kD: branch-free final row filters, 2 rows/thread, 4 uint2 loads per row.
// ===========================================================================
template <int R, int C>
__global__ void __launch_bounds__(256)
kD(const uint2* __restrict__ yp, float* __restrict__ out) {
    constexpr int P = C / 4, PS2 = (C + 10) / 2;
    constexpr int LP = ilog2c(P);
    unsigned idx = blockIdx.x * 256u + threadIdx.x;
    int p = idx & (P - 1);
    int rp = idx >> LP;
    int row0 = 2 * rp;

#pragma unroll
    for (int rr = 0; rr < 2; rr++) {
        int row = row0 + rr;
        const uint2* q = yp + (size_t)row * PS2 + (2 * p + 1);
        uint2 v0 = __ldg(q), v1 = __ldg(q + 1), v2 = __ldg(q + 2), v3 = __ldg(q + 3);
        float2 f0 = unpk_lo(v0), f1 = unpk_lo(v1), f2 = unpk_lo(v2), f3 = unpk_lo(v3);
        float2 g0 = unpk_hi(v0), g1 = unpk_hi(v1), g2 = unpk_hi(v2), g3 = unpk_hi(v3);
        float a[6], v[8];
        a[0] = f0.y; a[1] = f1.x; a[2] = f1.y; a[3] = f2.x; a[4] = f2.y; a[5] = f3.x;
        v[0] = g0.x; v[1] = g0.y; v[2] = g1.x; v[3] = g1.y;
        v[4] = g2.x; v[5] = g2.y; v[6] = g3.x; v[7] = g3.y;
        float4 o;
        o.x = G0 * (a[0] + a[2]) + G1 * a[1] + Q_E * (v[0] + v[4]) + Q_D * (v[1] + v[3]) + Q_F * v[2];
        o.y = G0 * (a[1] + a[3]) + G1 * a[2] + Q_E * (v[1] + v[5]) + Q_D * (v[2] + v[4]) + Q_F * v[3];
        o.z = G0 * (a[2] + a[4]) + G1 * a[3] + Q_E * (v[2] + v[6]) + Q_D * (v[3] + v[5]) + Q_F * v[4];
        o.w = G0 * (a[3] + a[5]) + G1 * a[4] + Q_E * (v[3] + v[7]) + Q_D * (v[4] + v[6]) + Q_F * v[5];
        reinterpret_cast<float4*>(out + (size_t)row * C)[p] = o;
    }
}

extern "C" void kernel_launch(void* const* d_in, const int* in_sizes, int n_in,
                              void* d_out, int out_size) {
    const float *yl = nullptr, *yh0 = nullptr, *yh1 = nullptr, *yh2 = nullptr;
    for (int i = 0; i < n_in; i++) {
        switch (in_sizes[i]) {
            case 524288:   yl  = (const float*)d_in[i]; break;  // 128*64*64
            case 25165824: yh0 = (const float*)d_in[i]; break;  // 128*6*128*128*2
            case 6291456:  yh1 = (const float*)d_in[i]; break;  // 128*6*64*64*2
            case 1572864:  yh2 = (const float*)d_in[i]; break;  // 128*6*32*32*2
            default: break;
        }
    }

    uint2* pyp;
    __half *pz128, *pz256;
    cudaGetSymbolAddress((void**)&pyp,   g_yp);
    cudaGetSymbolAddress((void**)&pz128, g_z128);
    cudaGetSymbolAddress((void**)&pz256, g_z256);

    // Level 1: (64,64) -> (128,128)
    kA<64, 64, float><<<128 * 32 * 37 / 256, 256>>>(yl, yh2, pyp);
    kB<128, 128><<<128 * 64 * 32 / 256, 256>>>(pyp, pz128);

    // Level 2: (128,128) -> (256,256)
    kA<128, 128, __half><<<128 * 64 * 69 / 256, 256>>>(pz128, yh1, pyp);
    kB<256, 256><<<128 * 128 * 64 / 256, 256>>>(pyp, pz256);

    // Final level
    kC<256, 256><<<128 * 64 * 133 / 256, 256>>>(pz256, yh0, pyp);
    kD<256, 256><<<128 * 128 * 64 / 256, 256>>>(pyp, (float*)d_out);
}